// round 3
// baseline (speedup 1.0000x reference)
#include <cuda_runtime.h>
#include <cstdio>

// ---------------------------------------------------------------------------
// AttentionBlock: B=16, C=512, H=W=32 (L=1024), 32 groups, 8 heads (ch=64)
// Pipeline: GroupNorm -> qkv GEMM -> flash attention -> proj GEMM + residual
// All fp32.
// ---------------------------------------------------------------------------

#define Bsz  16
#define Cch  512
#define Lsp  1024
#define NG   32
#define NH   8
#define CH   64           // channels per head
#define EPSV 1e-4f

// Scratch (static device arrays; allocation is forbidden)
__device__ float g_xn [Bsz * Cch  * Lsp];           // 32 MB
__device__ float g_qkv[Bsz * 3*Cch * Lsp];          // 96 MB
__device__ float g_a  [Bsz * Cch  * Lsp];           // 32 MB

// ---------------------------------------------------------------------------
// Kernel 1: GroupNorm. One block per (batch, group): 16 channels x 1024.
// ---------------------------------------------------------------------------
__global__ __launch_bounds__(256) void gn_kernel(
    const float* __restrict__ x, const float* __restrict__ w,
    const float* __restrict__ bb, float* __restrict__ xn)
{
    int batch = blockIdx.x >> 5;
    int g     = blockIdx.x & 31;
    const size_t base = ((size_t)batch * Cch + (size_t)g * 16) * Lsp;
    const float* xp = x  + base;
    float*       op = xn + base;

    float s = 0.f, s2 = 0.f;
    for (int i = threadIdx.x * 4; i < 16 * Lsp; i += 256 * 4) {
        float4 v = *(const float4*)(xp + i);
        s  += v.x + v.y + v.z + v.w;
        s2 += v.x*v.x + v.y*v.y + v.z*v.z + v.w*v.w;
    }
    #pragma unroll
    for (int o = 16; o; o >>= 1) {
        s  += __shfl_xor_sync(0xffffffffu, s,  o);
        s2 += __shfl_xor_sync(0xffffffffu, s2, o);
    }
    __shared__ float sA[8], sB[8];
    int warp = threadIdx.x >> 5, lane = threadIdx.x & 31;
    if (lane == 0) { sA[warp] = s; sB[warp] = s2; }
    __syncthreads();
    if (threadIdx.x == 0) {
        float S = 0.f, S2 = 0.f;
        #pragma unroll
        for (int i = 0; i < 8; i++) { S += sA[i]; S2 += sB[i]; }
        float mu  = S  * (1.f / (16.f * Lsp));
        float var = S2 * (1.f / (16.f * Lsp)) - mu * mu;
        sA[0] = mu;
        sB[0] = rsqrtf(var + EPSV);
    }
    __syncthreads();
    float mu = sA[0], rstd = sB[0];

    for (int i = threadIdx.x * 4; i < 16 * Lsp; i += 256 * 4) {
        int c = g * 16 + (i >> 10);
        float sw = w[c] * rstd;
        float sb = bb[c] - mu * sw;
        float4 v = *(const float4*)(xp + i);
        v.x = v.x * sw + sb;  v.y = v.y * sw + sb;
        v.z = v.z * sw + sb;  v.w = v.w * sw + sb;
        *(float4*)(op + i) = v;
    }
}

// ---------------------------------------------------------------------------
// Kernel 2/4: batched SGEMM  C[b] = A @ B[b] + bias (+ resid[b])
// A: [M,K] row-major (weights, shared across batch). B: [K,1024]. N = 1024.
// 128x128 tile, BK=8, 256 threads, 8x8 microkernel, register prefetch.
// ---------------------------------------------------------------------------
__global__ __launch_bounds__(256, 2) void sgemm_bias(
    const float* __restrict__ A, const float* __restrict__ Bg,
    const float* __restrict__ bias, const float* __restrict__ resid,
    float* __restrict__ C, int M, int K)
{
    const int N = Lsp;
    __shared__ float As[8][128];
    __shared__ float Bs[8][128];

    int tid = threadIdx.x;
    int m0 = blockIdx.y << 7, n0 = blockIdx.x << 7;
    const float* Bp = Bg + (size_t)blockIdx.z * K * N;
    float*       Cp = C  + (size_t)blockIdx.z * M * N;
    const float* Rp = resid ? resid + (size_t)blockIdx.z * M * N : nullptr;

    int arow = tid >> 1,  acol = (tid & 1)  << 2;
    int brow = tid >> 5,  bcol = (tid & 31) << 2;
    const float* Aptr = A  + (size_t)(m0 + arow) * K + acol;
    const float* Bptr = Bp + (size_t)brow * N + n0 + bcol;

    int ty = tid >> 4, tx = tid & 15;

    float acc[8][8];
    #pragma unroll
    for (int i = 0; i < 8; i++)
        #pragma unroll
        for (int j = 0; j < 8; j++) acc[i][j] = 0.f;

    float4 aReg = *(const float4*)Aptr;
    float4 bReg = *(const float4*)Bptr;

    for (int k0 = 0; k0 < K; k0 += 8) {
        As[acol + 0][arow] = aReg.x;
        As[acol + 1][arow] = aReg.y;
        As[acol + 2][arow] = aReg.z;
        As[acol + 3][arow] = aReg.w;
        *(float4*)&Bs[brow][bcol] = bReg;
        __syncthreads();
        if (k0 + 8 < K) {
            aReg = *(const float4*)(Aptr + k0 + 8);
            bReg = *(const float4*)(Bptr + (size_t)(k0 + 8) * N);
        }
        #pragma unroll
        for (int kk = 0; kk < 8; kk++) {
            float4 a0 = *(float4*)&As[kk][ty * 8];
            float4 a1 = *(float4*)&As[kk][ty * 8 + 4];
            float4 b0 = *(float4*)&Bs[kk][tx * 8];
            float4 b1 = *(float4*)&Bs[kk][tx * 8 + 4];
            float av[8] = {a0.x, a0.y, a0.z, a0.w, a1.x, a1.y, a1.z, a1.w};
            float bv[8] = {b0.x, b0.y, b0.z, b0.w, b1.x, b1.y, b1.z, b1.w};
            #pragma unroll
            for (int i = 0; i < 8; i++)
                #pragma unroll
                for (int j = 0; j < 8; j++)
                    acc[i][j] += av[i] * bv[j];
        }
        __syncthreads();
    }

    #pragma unroll
    for (int i = 0; i < 8; i++) {
        int row = m0 + ty * 8 + i;
        float bz = bias[row];
        size_t off = (size_t)row * N + n0 + tx * 8;
        float4 o0, o1;
        o0.x = acc[i][0] + bz; o0.y = acc[i][1] + bz;
        o0.z = acc[i][2] + bz; o0.w = acc[i][3] + bz;
        o1.x = acc[i][4] + bz; o1.y = acc[i][5] + bz;
        o1.z = acc[i][6] + bz; o1.w = acc[i][7] + bz;
        if (Rp) {
            float4 r0 = *(const float4*)(Rp + off);
            float4 r1 = *(const float4*)(Rp + off + 4);
            o0.x += r0.x; o0.y += r0.y; o0.z += r0.z; o0.w += r0.w;
            o1.x += r1.x; o1.y += r1.y; o1.z += r1.z; o1.w += r1.w;
        }
        *(float4*)(Cp + off)     = o0;
        *(float4*)(Cp + off + 4) = o1;
    }
}

// ---------------------------------------------------------------------------
// Kernel 3: flash attention.
// grid: (t_tile=16, bh=128), 256 threads. Tiles: 64 t x 64 s, ch = 64.
// SMEM: Qs[64][68], Ks[64][68] (both [ch][t/s]), Vts[64][68] ([s][ch]),
//       Pts[64][68] ([s][t]).
// Thread layout: tg = tid/16 owns t rows tg*4..+3 (both phases);
//   S phase: sg = tid%16 owns s cols sg*4..+3;
//   AV phase: cg = tid%16 owns ch rows cg*4..+3.
// ---------------------------------------------------------------------------
#define STR 68
#define ATT_SMEM (4 * 64 * STR * (int)sizeof(float))

__global__ __launch_bounds__(256) void attn_kernel(
    const float* __restrict__ qkv, float* __restrict__ aout)
{
    extern __shared__ float sm[];
    float* Qs  = sm;
    float* Ks  = sm + 64 * STR;
    float* Vts = sm + 2 * 64 * STR;
    float* Pts = sm + 3 * 64 * STR;

    int tid = threadIdx.x;
    int bh = blockIdx.y;
    int batch = bh >> 3, h = bh & 7;
    size_t base = (size_t)batch * (3 * Cch) * Lsp;
    const float* Qp = qkv + base + (size_t)(h * CH) * Lsp;
    const float* Kp = qkv + base + (size_t)(Cch + h * CH) * Lsp;
    const float* Vp = qkv + base + (size_t)(2 * Cch + h * CH) * Lsp;
    float* Ap = aout + ((size_t)batch * Cch + (size_t)h * CH) * Lsp;

    int t0 = blockIdx.x * 64;
    int tg = tid >> 4;            // 0..15
    int sg = tid & 15;            // 0..15 (also cg in AV phase)
    int lrow = tid >> 4;          // loader row base (ch)
    int lcol = (tid & 15) << 2;   // loader col base

    const float sc2 = 0.125f;     // ch^-0.5 = 1/8 (both q and k scales folded)

    // Load Q tile [ch][t], pre-scaled
    #pragma unroll
    for (int r = 0; r < 4; r++) {
        int row = lrow + (r << 4);
        float4 q4 = *(const float4*)(Qp + (size_t)row * Lsp + t0 + lcol);
        q4.x *= sc2; q4.y *= sc2; q4.z *= sc2; q4.w *= sc2;
        *(float4*)(Qs + row * STR + lcol) = q4;
    }

    float acc[4][4];
    #pragma unroll
    for (int i = 0; i < 4; i++)
        #pragma unroll
        for (int j = 0; j < 4; j++) acc[i][j] = 0.f;
    float m_t[4] = {-INFINITY, -INFINITY, -INFINITY, -INFINITY};
    float l_t[4] = {0.f, 0.f, 0.f, 0.f};

    for (int s0 = 0; s0 < Lsp; s0 += 64) {
        __syncthreads();   // protect Ks/Vts/Pts from previous iteration readers
        // Load K [ch][s] and V (transposed -> Vts[s][ch])
        #pragma unroll
        for (int r = 0; r < 4; r++) {
            int row = lrow + (r << 4);
            float4 k4 = *(const float4*)(Kp + (size_t)row * Lsp + s0 + lcol);
            *(float4*)(Ks + row * STR + lcol) = k4;
            float4 v4 = *(const float4*)(Vp + (size_t)row * Lsp + s0 + lcol);
            Vts[(lcol + 0) * STR + row] = v4.x;
            Vts[(lcol + 1) * STR + row] = v4.y;
            Vts[(lcol + 2) * STR + row] = v4.z;
            Vts[(lcol + 3) * STR + row] = v4.w;
        }
        __syncthreads();

        // S = Q^T K  (4x4 outer product per thread)
        float Sv[4][4];
        #pragma unroll
        for (int i = 0; i < 4; i++)
            #pragma unroll
            for (int j = 0; j < 4; j++) Sv[i][j] = 0.f;
        #pragma unroll 8
        for (int ch = 0; ch < CH; ch++) {
            float4 q4 = *(const float4*)(Qs + ch * STR + (tg << 2));
            float4 k4 = *(const float4*)(Ks + ch * STR + (sg << 2));
            float qv[4] = {q4.x, q4.y, q4.z, q4.w};
            float kv[4] = {k4.x, k4.y, k4.z, k4.w};
            #pragma unroll
            for (int i = 0; i < 4; i++)
                #pragma unroll
                for (int j = 0; j < 4; j++)
                    Sv[i][j] += qv[i] * kv[j];
        }

        // Online softmax over the 16-thread row group (lanes differ only in sg)
        float alpha[4];
        #pragma unroll
        for (int i = 0; i < 4; i++) {
            float rmax = fmaxf(fmaxf(Sv[i][0], Sv[i][1]), fmaxf(Sv[i][2], Sv[i][3]));
            #pragma unroll
            for (int o = 8; o; o >>= 1)
                rmax = fmaxf(rmax, __shfl_xor_sync(0xffffffffu, rmax, o));
            float mnew = fmaxf(m_t[i], rmax);
            alpha[i] = __expf(m_t[i] - mnew);
            float rsum = 0.f;
            #pragma unroll
            for (int j = 0; j < 4; j++) {
                float p = __expf(Sv[i][j] - mnew);
                Sv[i][j] = p;
                rsum += p;
            }
            #pragma unroll
            for (int o = 8; o; o >>= 1)
                rsum += __shfl_xor_sync(0xffffffffu, rsum, o);
            l_t[i] = l_t[i] * alpha[i] + rsum;
            m_t[i] = mnew;
        }
        // Write P transposed: Pts[s][t]
        #pragma unroll
        for (int j = 0; j < 4; j++)
            #pragma unroll
            for (int i = 0; i < 4; i++)
                Pts[((sg << 2) + j) * STR + (tg << 2) + i] = Sv[i][j];
        __syncthreads();

        // O[ch][t] = O*alpha + V @ P   (cg = sg reinterpretated as ch group)
        #pragma unroll
        for (int i = 0; i < 4; i++)
            #pragma unroll
            for (int j = 0; j < 4; j++)
                acc[i][j] *= alpha[j];
        #pragma unroll 8
        for (int s = 0; s < 64; s++) {
            float4 p4 = *(const float4*)(Pts + s * STR + (tg << 2));
            float4 v4 = *(const float4*)(Vts + s * STR + (sg << 2));
            float pv[4] = {p4.x, p4.y, p4.z, p4.w};
            float vv[4] = {v4.x, v4.y, v4.z, v4.w};
            #pragma unroll
            for (int i = 0; i < 4; i++)
                #pragma unroll
                for (int j = 0; j < 4; j++)
                    acc[i][j] += vv[i] * pv[j];
        }
    }

    // Normalize and stage into SMEM (reuse Qs as Os[ch][t]) for coalesced write
    #pragma unroll
    for (int j = 0; j < 4; j++) {
        float inv = 1.f / l_t[j];
        #pragma unroll
        for (int i = 0; i < 4; i++)
            Qs[((sg << 2) + i) * STR + (tg << 2) + j] = acc[i][j] * inv;
    }
    __syncthreads();
    for (int idx = tid; idx < 64 * 64 / 4; idx += 256) {
        int ch = idx >> 4;
        int t  = (idx & 15) << 2;
        *(float4*)(Ap + (size_t)ch * Lsp + t0 + t) = *(float4*)(Qs + ch * STR + t);
    }
}

// ---------------------------------------------------------------------------
// Launch
// ---------------------------------------------------------------------------
extern "C" void kernel_launch(void* const* d_in, const int* in_sizes, int n_in,
                              void* d_out, int out_size)
{
    const float* x      = (const float*)d_in[0];
    const float* norm_w = (const float*)d_in[1];
    const float* norm_b = (const float*)d_in[2];
    const float* qkv_w  = (const float*)d_in[3];
    const float* qkv_b  = (const float*)d_in[4];
    const float* proj_w = (const float*)d_in[5];
    const float* proj_b = (const float*)d_in[6];
    float* out = (float*)d_out;

    float *xn, *qkv, *a_;
    cudaGetSymbolAddress((void**)&xn,  g_xn);
    cudaGetSymbolAddress((void**)&qkv, g_qkv);
    cudaGetSymbolAddress((void**)&a_,  g_a);

    // 1. GroupNorm
    gn_kernel<<<Bsz * NG, 256>>>(x, norm_w, norm_b, xn);

    // 2. qkv GEMM: [1536,512] @ [512,1024] per batch
    sgemm_bias<<<dim3(Lsp / 128, (3 * Cch) / 128, Bsz), 256>>>(
        qkv_w, xn, qkv_b, nullptr, qkv, 3 * Cch, Cch);

    // 3. Flash attention
    cudaFuncSetAttribute(attn_kernel, cudaFuncAttributeMaxDynamicSharedMemorySize,
                         ATT_SMEM);
    attn_kernel<<<dim3(Lsp / 64, Bsz * NH), 256, ATT_SMEM>>>(qkv, a_);

    // 4. proj GEMM + bias + residual -> out
    sgemm_bias<<<dim3(Lsp / 128, Cch / 128, Bsz), 256>>>(
        proj_w, a_, proj_b, x, out, Cch, Cch);
}

// round 8
// speedup vs baseline: 2.4481x; 2.4481x over previous
#include <cuda_runtime.h>
#include <cuda_bf16.h>
#include <cstdint>

// ---------------------------------------------------------------------------
// AttentionBlock: B=16, C=512, H=W=32 (L=1024), 32 groups, 8 heads (ch=64)
// Pipeline: GroupNorm(->bf16 hi/lo, transposed) -> mma.sync qkv GEMM (bf16
// hi/lo out, q pre-scaled) -> mma.sync flash attention (bf16 hi/lo out,
// transposed) -> mma.sync proj GEMM + bias + residual -> fp32 out.
// All matmuls: split-bf16 (hi+lo), 3 MMAs ~ fp32 precision, via
// mma.sync.m16n8k16 (sm_80 PTX path; tcgen05 unavailable on this target).
// ---------------------------------------------------------------------------

#define Bsz  16
#define Cch  512
#define Lsp  1024
#define NH   8
#define CH   64
#define EPSV 1e-4f

// Scratch (static device arrays; allocation is forbidden)
__device__ __nv_bfloat16 g_xth[Bsz * Lsp * Cch];   // X^T hi [b][l][c]
__device__ __nv_bfloat16 g_xtl[Bsz * Lsp * Cch];   // X^T lo
__device__ __nv_bfloat16 g_qh [Bsz * 3*Cch * Lsp]; // qkv hi [b][3C][l] (q scaled)
__device__ __nv_bfloat16 g_ql [Bsz * 3*Cch * Lsp]; // qkv lo
__device__ __nv_bfloat16 g_ath[Bsz * Lsp * Cch];   // A^T hi [b][l][c]
__device__ __nv_bfloat16 g_atl[Bsz * Lsp * Cch];   // A^T lo
__device__ __nv_bfloat16 g_wqh[3*Cch * Cch];       // qkv_w hi [M,K]
__device__ __nv_bfloat16 g_wql[3*Cch * Cch];
__device__ __nv_bfloat16 g_wph[Cch * Cch];         // proj_w hi
__device__ __nv_bfloat16 g_wpl[Cch * Cch];

// ---------------------------------------------------------------------------
// PTX helpers (sm_80-class: mma.sync + ldmatrix + cp.async)
// ---------------------------------------------------------------------------
__device__ __forceinline__ uint32_t smem_to_u32(const void* p) {
    uint32_t a;
    asm("{ .reg .u64 t; cvta.to.shared.u64 t, %1; cvt.u32.u64 %0, t; }"
        : "=r"(a) : "l"(p));
    return a;
}

__device__ __forceinline__ void mma_bf16(float* d, const uint32_t* a, const uint32_t* b) {
    asm volatile(
        "mma.sync.aligned.m16n8k16.row.col.f32.bf16.bf16.f32 "
        "{%0,%1,%2,%3}, {%4,%5,%6,%7}, {%8,%9}, {%0,%1,%2,%3};\n"
        : "+f"(d[0]), "+f"(d[1]), "+f"(d[2]), "+f"(d[3])
        : "r"(a[0]), "r"(a[1]), "r"(a[2]), "r"(a[3]), "r"(b[0]), "r"(b[1]));
}
__device__ __forceinline__ void ldsm_x4(uint32_t* r, uint32_t addr) {
    asm volatile("ldmatrix.sync.aligned.m8n8.x4.shared.b16 {%0,%1,%2,%3}, [%4];"
        : "=r"(r[0]), "=r"(r[1]), "=r"(r[2]), "=r"(r[3]) : "r"(addr));
}
__device__ __forceinline__ void ldsm_x4_trans(uint32_t* r, uint32_t addr) {
    asm volatile("ldmatrix.sync.aligned.m8n8.x4.trans.shared.b16 {%0,%1,%2,%3}, [%4];"
        : "=r"(r[0]), "=r"(r[1]), "=r"(r[2]), "=r"(r[3]) : "r"(addr));
}
__device__ __forceinline__ void ldsm_x2(uint32_t* r, uint32_t addr) {
    asm volatile("ldmatrix.sync.aligned.m8n8.x2.shared.b16 {%0,%1}, [%2];"
        : "=r"(r[0]), "=r"(r[1]) : "r"(addr));
}
__device__ __forceinline__ void ldsm_x2_trans(uint32_t* r, uint32_t addr) {
    asm volatile("ldmatrix.sync.aligned.m8n8.x2.trans.shared.b16 {%0,%1}, [%2];"
        : "=r"(r[0]), "=r"(r[1]) : "r"(addr));
}
#define CP_ASYNC16(sm, gm) \
    asm volatile("cp.async.cg.shared.global [%0], [%1], 16;" :: "r"(sm), "l"(gm))
#define CP_COMMIT() asm volatile("cp.async.commit_group;" ::: "memory")
#define CP_WAIT1()  asm volatile("cp.async.wait_group 1;" ::: "memory")
#define CP_WAIT0()  asm volatile("cp.async.wait_group 0;" ::: "memory")

// hi/lo bf16 split of two floats, packed as bf16x2 words (lo half = first)
__device__ __forceinline__ void split2(float v0, float v1, uint32_t& hp, uint32_t& lp) {
    __nv_bfloat16 h0 = __float2bfloat16(v0);
    __nv_bfloat16 h1 = __float2bfloat16(v1);
    __nv_bfloat16 l0 = __float2bfloat16(v0 - __bfloat162float(h0));
    __nv_bfloat16 l1 = __float2bfloat16(v1 - __bfloat162float(h1));
    hp = (uint32_t)__bfloat16_as_ushort(h0) | ((uint32_t)__bfloat16_as_ushort(h1) << 16);
    lp = (uint32_t)__bfloat16_as_ushort(l0) | ((uint32_t)__bfloat16_as_ushort(l1) << 16);
}

// ---------------------------------------------------------------------------
// Kernel: weight split fp32 -> bf16 hi/lo
// ---------------------------------------------------------------------------
__global__ __launch_bounds__(256) void wsplit_kernel(
    const float* __restrict__ in, __nv_bfloat16* __restrict__ hi,
    __nv_bfloat16* __restrict__ lo, int n4)
{
    int i = blockIdx.x * 256 + threadIdx.x;
    if (i >= n4) return;
    float4 v = ((const float4*)in)[i];
    uint32_t h0, l0, h1, l1;
    split2(v.x, v.y, h0, l0);
    split2(v.z, v.w, h1, l1);
    ((uint2*)hi)[i] = make_uint2(h0, h1);
    ((uint2*)lo)[i] = make_uint2(l0, l1);
}

// ---------------------------------------------------------------------------
// Kernel: GroupNorm -> transposed bf16 hi/lo  Xt[b][l][c]
// ---------------------------------------------------------------------------
#define SM8S 1028
__global__ __launch_bounds__(256) void gn_kernel(
    const float* __restrict__ x, const float* __restrict__ w,
    const float* __restrict__ bb,
    __nv_bfloat16* __restrict__ xth, __nv_bfloat16* __restrict__ xtl)
{
    int batch = blockIdx.x >> 5;
    int g     = blockIdx.x & 31;
    const size_t base = ((size_t)batch * Cch + (size_t)g * 16) * Lsp;
    const float* xp = x + base;

    float s = 0.f, s2 = 0.f;
    for (int i = threadIdx.x * 4; i < 16 * Lsp; i += 256 * 4) {
        float4 v = *(const float4*)(xp + i);
        s  += v.x + v.y + v.z + v.w;
        s2 += v.x*v.x + v.y*v.y + v.z*v.z + v.w*v.w;
    }
    #pragma unroll
    for (int o = 16; o; o >>= 1) {
        s  += __shfl_xor_sync(0xffffffffu, s,  o);
        s2 += __shfl_xor_sync(0xffffffffu, s2, o);
    }
    __shared__ float sA[8], sB[8];
    __shared__ float sm8[8 * SM8S];
    int warp = threadIdx.x >> 5, lane = threadIdx.x & 31;
    if (lane == 0) { sA[warp] = s; sB[warp] = s2; }
    __syncthreads();
    if (threadIdx.x == 0) {
        float S = 0.f, S2 = 0.f;
        #pragma unroll
        for (int i = 0; i < 8; i++) { S += sA[i]; S2 += sB[i]; }
        float mu  = S  * (1.f / (16.f * Lsp));
        float var = S2 * (1.f / (16.f * Lsp)) - mu * mu;
        sA[0] = mu;
        sB[0] = rsqrtf(var + EPSV);
    }
    __syncthreads();
    float mu = sA[0], rstd = sB[0];
    int tid = threadIdx.x;

    #pragma unroll
    for (int half = 0; half < 2; half++) {
        if (half) __syncthreads();
        for (int i = tid * 4; i < 8 * Lsp; i += 256 * 4) {
            int r = i >> 10, col = i & 1023;
            int c = g * 16 + half * 8 + r;
            float sw = w[c] * rstd;
            float sb = bb[c] - mu * sw;
            float4 v = *(const float4*)(xp + (size_t)(half * 8 + r) * Lsp + col);
            v.x = v.x * sw + sb; v.y = v.y * sw + sb;
            v.z = v.z * sw + sb; v.w = v.w * sw + sb;
            *(float4*)(&sm8[r * SM8S + col]) = v;
        }
        __syncthreads();
        for (int n = tid; n < Lsp; n += 256) {
            uint32_t hp[4], lp[4];
            #pragma unroll
            for (int c2 = 0; c2 < 4; c2++)
                split2(sm8[(2*c2) * SM8S + n], sm8[(2*c2+1) * SM8S + n], hp[c2], lp[c2]);
            size_t o = ((size_t)batch * Lsp + n) * Cch + g * 16 + half * 8;
            *(uint4*)(xth + o) = make_uint4(hp[0], hp[1], hp[2], hp[3]);
            *(uint4*)(xtl + o) = make_uint4(lp[0], lp[1], lp[2], lp[3]);
        }
    }
}

// ---------------------------------------------------------------------------
// Kernel: split-bf16 GEMM via mma.sync.
// C[b][m][n] = sum_k W[m][k]*X[b][n][k] (+bias) [mode fp32: +resid -> C]
//                                               [mode bf16: qscale, -> Oh/Ol]
// CTA 128x128, BK=32, cp.async double-buffered, 8 warps of 32x64.
// ---------------------------------------------------------------------------
#define GPAD   40                        // bf16 elems per SMEM row (32+8)
#define GPLB   (128 * GPAD * 2)          // plane bytes = 10240
#define GSTGB  (4 * GPLB)                // stage bytes = 40960
#define GSMEM  (2 * GSTGB)               // 81920

__global__ __launch_bounds__(256) void gemm_mma(
    const __nv_bfloat16* __restrict__ Wh, const __nv_bfloat16* __restrict__ Wl,
    const __nv_bfloat16* __restrict__ Xh, const __nv_bfloat16* __restrict__ Xl,
    const float* __restrict__ bias, const float* __restrict__ resid,
    float* __restrict__ C,
    __nv_bfloat16* __restrict__ Oh, __nv_bfloat16* __restrict__ Ol, int M)
{
    extern __shared__ char smem[];
    uint32_t sb = smem_to_u32(smem);
    int tid = threadIdx.x;
    int wid = tid >> 5, lane = tid & 31;
    int m0 = blockIdx.y << 7, n0 = blockIdx.x << 7, b = blockIdx.z;

    // per-thread load slots: 8 chunks of 16B per stage
    const __nv_bfloat16* gsrc[8];
    uint32_t soff[8];
    #pragma unroll
    for (int i = 0; i < 8; i++) {
        int c = i * 256 + tid;
        int plane = c >> 9, row = (c >> 2) & 127, kc = c & 3;
        const __nv_bfloat16* gp;
        if      (plane == 0) gp = Wh + (size_t)(m0 + row) * Cch;
        else if (plane == 1) gp = Wl + (size_t)(m0 + row) * Cch;
        else if (plane == 2) gp = Xh + ((size_t)b * Lsp + n0 + row) * Cch;
        else                 gp = Xl + ((size_t)b * Lsp + n0 + row) * Cch;
        gsrc[i] = gp + kc * 8;
        soff[i] = plane * GPLB + row * (GPAD * 2) + kc * 16;
    }

    // prologue: stage 0
    #pragma unroll
    for (int i = 0; i < 8; i++) CP_ASYNC16(sb + soff[i], gsrc[i]);
    CP_COMMIT();

    int wm = wid >> 1, wn = wid & 1;
    float acc[2][8][4];
    #pragma unroll
    for (int mt = 0; mt < 2; mt++)
        #pragma unroll
        for (int nt = 0; nt < 8; nt++)
            #pragma unroll
            for (int q = 0; q < 4; q++) acc[mt][nt][q] = 0.f;

    #pragma unroll 1
    for (int s = 0; s < 16; s++) {
        if (s + 1 < 16) {
            int k0 = (s + 1) * 32;
            uint32_t nbuf = ((s + 1) & 1) * GSTGB;
            #pragma unroll
            for (int i = 0; i < 8; i++) CP_ASYNC16(sb + nbuf + soff[i], gsrc[i] + k0);
            CP_COMMIT();
            CP_WAIT1();
        } else {
            CP_WAIT0();
        }
        __syncthreads();

        uint32_t sbase = sb + (s & 1) * GSTGB;
        #pragma unroll
        for (int ks = 0; ks < 2; ks++) {
            uint32_t ah[2][4], al[2][4];
            #pragma unroll
            for (int mt = 0; mt < 2; mt++) {
                uint32_t ao = sbase +
                    ((wm * 32 + mt * 16 + (lane & 15)) * GPAD + ks * 16 + ((lane >> 4) << 3)) * 2;
                ldsm_x4(ah[mt], ao);
                ldsm_x4(al[mt], ao + GPLB);
            }
            #pragma unroll
            for (int ntp = 0; ntp < 4; ntp++) {
                uint32_t bo = sbase + 2 * GPLB +
                    ((wn * 64 + ntp * 16 + (lane & 7) + ((lane >> 4) << 3)) * GPAD
                     + ks * 16 + (((lane >> 3) & 1) << 3)) * 2;
                uint32_t bh[4], bl[4];
                ldsm_x4(bh, bo);
                ldsm_x4(bl, bo + GPLB);
                #pragma unroll
                for (int mt = 0; mt < 2; mt++)
                    #pragma unroll
                    for (int sub = 0; sub < 2; sub++) {
                        float* d = acc[mt][ntp * 2 + sub];
                        mma_bf16(d, ah[mt], bh + sub * 2);
                        mma_bf16(d, ah[mt], bl + sub * 2);
                        mma_bf16(d, al[mt], bh + sub * 2);
                    }
            }
        }
        __syncthreads();
    }

    // epilogue
    #pragma unroll
    for (int mt = 0; mt < 2; mt++) {
        int r0 = m0 + wm * 32 + mt * 16 + (lane >> 2);
        #pragma unroll
        for (int half = 0; half < 2; half++) {
            int r = r0 + half * 8;
            float bz = bias[r];
            #pragma unroll
            for (int nt = 0; nt < 8; nt++) {
                int col = n0 + wn * 64 + nt * 8 + 2 * (lane & 3);
                float v0 = acc[mt][nt][half * 2 + 0] + bz;
                float v1 = acc[mt][nt][half * 2 + 1] + bz;
                if (C) {
                    size_t o = ((size_t)b * M + r) * Lsp + col;
                    float2 rv = *(const float2*)(resid + o);
                    float2 ov = make_float2(v0 + rv.x, v1 + rv.y);
                    *(float2*)(C + o) = ov;
                } else {
                    if (r < Cch) { v0 *= 0.125f; v1 *= 0.125f; }   // q pre-scale
                    uint32_t hp, lp;
                    split2(v0, v1, hp, lp);
                    size_t o = ((size_t)b * M + r) * Lsp + col;
                    *(uint32_t*)(Oh + o) = hp;
                    *(uint32_t*)(Ol + o) = lp;
                }
            }
        }
    }
}

// ---------------------------------------------------------------------------
// Kernel: flash attention via mma.sync, split-bf16.
// grid (16 t-tiles, 128 bh), 128 threads (4 warps x m16 rows of t).
// SMEM planes (bf16, [64 rows][72]): Qh Ql Kh Kl Vh Vl.
// Q/K stored [ch][t|s] -> A/B frags via ldmatrix .trans; V [ch][s] -> non-trans.
// ---------------------------------------------------------------------------
#define APAD   72
#define APLB   (64 * APAD * 2)     // plane bytes = 9216
#define ASMEM  (6 * APLB)          // 55296

__global__ __launch_bounds__(128) void attn_mma(
    const __nv_bfloat16* __restrict__ qh, const __nv_bfloat16* __restrict__ ql,
    __nv_bfloat16* __restrict__ ath, __nv_bfloat16* __restrict__ atl)
{
    extern __shared__ char smem[];
    uint32_t sb = smem_to_u32(smem);
    int tid = threadIdx.x;
    int wid = tid >> 5, lane = tid & 31;
    int bh = blockIdx.y;
    int batch = bh >> 3, h = bh & 7;
    int t0 = blockIdx.x << 6;

    size_t qrow = (size_t)batch * (3 * Cch) + h * CH;          // Q plane rows
    size_t krow = qrow + Cch;
    size_t vrow = qrow + 2 * Cch;

    // stage Q (2 planes x 64 rows x 8 chunks = 1024 chunks / 128 thr = 8)
    #pragma unroll
    for (int i = 0; i < 8; i++) {
        int c = i * 128 + tid;
        int plane = c >> 9, row = (c >> 3) & 63, cc = c & 7;
        const __nv_bfloat16* src = (plane ? ql : qh) + (qrow + row) * Lsp + t0 + cc * 8;
        uint4 v = *(const uint4*)src;
        *(uint4*)(smem + plane * APLB + row * (APAD * 2) + cc * 16) = v;
    }
    __syncthreads();

    // Q fragments (A, m=t k=ch), register-resident
    uint32_t aqh[4][4], aql[4][4];
    {
        int mbase = wid * 16;
        #pragma unroll
        for (int k = 0; k < 4; k++) {
            uint32_t ao = sb +
                ((k * 16 + ((lane >> 4) << 3) + (lane & 7)) * APAD
                 + mbase + (((lane >> 3) & 1) << 3)) * 2;
            ldsm_x4_trans(aqh[k], ao);
            ldsm_x4_trans(aql[k], ao + APLB);
        }
    }

    float Oacc[8][4];
    #pragma unroll
    for (int nt = 0; nt < 8; nt++)
        #pragma unroll
        for (int q = 0; q < 4; q++) Oacc[nt][q] = 0.f;
    float mrow0 = -INFINITY, mrow1 = -INFINITY, lrow0 = 0.f, lrow1 = 0.f;

    #pragma unroll 1
    for (int s0 = 0; s0 < Lsp; s0 += 64) {
        __syncthreads();    // prior iteration's K/V consumers done
        // stage K,V hi/lo (4 planes x 512 chunks / 128 thr = 16)
        #pragma unroll
        for (int i = 0; i < 16; i++) {
            int c = i * 128 + tid;
            int plane = c >> 9, row = (c >> 3) & 63, cc = c & 7;
            size_t grow = (plane < 2 ? krow : vrow) + row;
            const __nv_bfloat16* src = ((plane & 1) ? ql : qh) + grow * Lsp + s0 + cc * 8;
            uint4 v = *(const uint4*)src;
            *(uint4*)(smem + (2 + plane) * APLB + row * (APAD * 2) + cc * 16) = v;
        }
        __syncthreads();

        // S = Q K^T  (split: hh + hl + lh)
        float S[8][4];
        #pragma unroll
        for (int nt = 0; nt < 8; nt++) {
            S[nt][0] = S[nt][1] = S[nt][2] = S[nt][3] = 0.f;
            #pragma unroll
            for (int k = 0; k < 4; k++) {
                uint32_t ko = sb + 2 * APLB +
                    ((k * 16 + (lane & 15)) * APAD + nt * 8) * 2;
                uint32_t bh2[2], bl2[2];
                ldsm_x2_trans(bh2, ko);
                ldsm_x2_trans(bl2, ko + APLB);
                mma_bf16(S[nt], aqh[k], bh2);
                mma_bf16(S[nt], aqh[k], bl2);
                mma_bf16(S[nt], aql[k], bh2);
            }
        }

        // online softmax (rows: r=lane/4 -> c0,c1 ; r+8 -> c2,c3)
        float mx0 = -INFINITY, mx1 = -INFINITY;
        #pragma unroll
        for (int nt = 0; nt < 8; nt++) {
            mx0 = fmaxf(mx0, fmaxf(S[nt][0], S[nt][1]));
            mx1 = fmaxf(mx1, fmaxf(S[nt][2], S[nt][3]));
        }
        #pragma unroll
        for (int o = 1; o <= 2; o <<= 1) {
            mx0 = fmaxf(mx0, __shfl_xor_sync(0xffffffffu, mx0, o));
            mx1 = fmaxf(mx1, __shfl_xor_sync(0xffffffffu, mx1, o));
        }
        float mn0 = fmaxf(mrow0, mx0), mn1 = fmaxf(mrow1, mx1);
        float alpha0 = __expf(mrow0 - mn0), alpha1 = __expf(mrow1 - mn1);
        mrow0 = mn0; mrow1 = mn1;
        float sum0 = 0.f, sum1 = 0.f;
        #pragma unroll
        for (int nt = 0; nt < 8; nt++) {
            S[nt][0] = __expf(S[nt][0] - mn0); sum0 += S[nt][0];
            S[nt][1] = __expf(S[nt][1] - mn0); sum0 += S[nt][1];
            S[nt][2] = __expf(S[nt][2] - mn1); sum1 += S[nt][2];
            S[nt][3] = __expf(S[nt][3] - mn1); sum1 += S[nt][3];
        }
        #pragma unroll
        for (int o = 1; o <= 2; o <<= 1) {
            sum0 += __shfl_xor_sync(0xffffffffu, sum0, o);
            sum1 += __shfl_xor_sync(0xffffffffu, sum1, o);
        }
        lrow0 = lrow0 * alpha0 + sum0;
        lrow1 = lrow1 * alpha1 + sum1;

        // pack P -> A frags (hi/lo), k = s dim: step j uses S tiles 2j, 2j+1
        uint32_t ph[4][4], pl[4][4];
        #pragma unroll
        for (int j = 0; j < 4; j++) {
            split2(S[2*j][0],   S[2*j][1],   ph[j][0], pl[j][0]);
            split2(S[2*j][2],   S[2*j][3],   ph[j][1], pl[j][1]);
            split2(S[2*j+1][0], S[2*j+1][1], ph[j][2], pl[j][2]);
            split2(S[2*j+1][2], S[2*j+1][3], ph[j][3], pl[j][3]);
        }

        // rescale O, then O += P V (split)
        #pragma unroll
        for (int nt = 0; nt < 8; nt++) {
            Oacc[nt][0] *= alpha0; Oacc[nt][1] *= alpha0;
            Oacc[nt][2] *= alpha1; Oacc[nt][3] *= alpha1;
        }
        #pragma unroll
        for (int nt = 0; nt < 8; nt++) {
            #pragma unroll
            for (int j = 0; j < 4; j++) {
                uint32_t vo = sb + 4 * APLB +
                    ((nt * 8 + (lane & 7)) * APAD + j * 16 + (((lane >> 3) & 1) << 3)) * 2;
                uint32_t vh2[2], vl2[2];
                ldsm_x2(vh2, vo);
                ldsm_x2(vl2, vo + APLB);
                mma_bf16(Oacc[nt], ph[j], vh2);
                mma_bf16(Oacc[nt], ph[j], vl2);
                mma_bf16(Oacc[nt], pl[j], vh2);
            }
        }
    }

    // epilogue: O /= l, split hi/lo, write transposed At[b][l][c]
    float inv0 = 1.f / lrow0, inv1 = 1.f / lrow1;
    int r0 = t0 + wid * 16 + (lane >> 2);
    int r1 = r0 + 8;
    #pragma unroll
    for (int nt = 0; nt < 8; nt++) {
        int col = h * CH + nt * 8 + 2 * (lane & 3);
        uint32_t hp, lp;
        split2(Oacc[nt][0] * inv0, Oacc[nt][1] * inv0, hp, lp);
        size_t o0 = ((size_t)batch * Lsp + r0) * Cch + col;
        *(uint32_t*)(ath + o0) = hp;
        *(uint32_t*)(atl + o0) = lp;
        split2(Oacc[nt][2] * inv1, Oacc[nt][3] * inv1, hp, lp);
        size_t o1 = ((size_t)batch * Lsp + r1) * Cch + col;
        *(uint32_t*)(ath + o1) = hp;
        *(uint32_t*)(atl + o1) = lp;
    }
}

// ---------------------------------------------------------------------------
// Launch
// ---------------------------------------------------------------------------
extern "C" void kernel_launch(void* const* d_in, const int* in_sizes, int n_in,
                              void* d_out, int out_size)
{
    const float* x      = (const float*)d_in[0];
    const float* norm_w = (const float*)d_in[1];
    const float* norm_b = (const float*)d_in[2];
    const float* qkv_w  = (const float*)d_in[3];
    const float* qkv_b  = (const float*)d_in[4];
    const float* proj_w = (const float*)d_in[5];
    const float* proj_b = (const float*)d_in[6];
    float* out = (float*)d_out;

    __nv_bfloat16 *xth, *xtl, *qh, *ql, *ath, *atl, *wqh, *wql, *wph, *wpl;
    cudaGetSymbolAddress((void**)&xth, g_xth);
    cudaGetSymbolAddress((void**)&xtl, g_xtl);
    cudaGetSymbolAddress((void**)&qh,  g_qh);
    cudaGetSymbolAddress((void**)&ql,  g_ql);
    cudaGetSymbolAddress((void**)&ath, g_ath);
    cudaGetSymbolAddress((void**)&atl, g_atl);
    cudaGetSymbolAddress((void**)&wqh, g_wqh);
    cudaGetSymbolAddress((void**)&wql, g_wql);
    cudaGetSymbolAddress((void**)&wph, g_wph);
    cudaGetSymbolAddress((void**)&wpl, g_wpl);

    cudaFuncSetAttribute(gemm_mma, cudaFuncAttributeMaxDynamicSharedMemorySize, GSMEM);
    cudaFuncSetAttribute(attn_mma, cudaFuncAttributeMaxDynamicSharedMemorySize, ASMEM);

    // 0. weight splits
    wsplit_kernel<<<(3*Cch*Cch/4 + 255)/256, 256>>>(qkv_w, wqh, wql, 3*Cch*Cch/4);
    wsplit_kernel<<<(Cch*Cch/4 + 255)/256, 256>>>(proj_w, wph, wpl, Cch*Cch/4);

    // 1. GroupNorm -> Xt hi/lo
    gn_kernel<<<Bsz * 32, 256>>>(x, norm_w, norm_b, xth, xtl);

    // 2. qkv GEMM -> bf16 hi/lo planes (q pre-scaled by 0.125)
    gemm_mma<<<dim3(Lsp/128, (3*Cch)/128, Bsz), 256, GSMEM>>>(
        wqh, wql, xth, xtl, qkv_b, nullptr, nullptr, qh, ql, 3*Cch);

    // 3. flash attention (mma) -> At hi/lo
    attn_mma<<<dim3(Lsp/64, Bsz*NH), 128, ASMEM>>>(qh, ql, ath, atl);

    // 4. proj GEMM + bias + residual -> fp32 out
    gemm_mma<<<dim3(Lsp/128, Cch/128, Bsz), 256, GSMEM>>>(
        wph, wpl, ath, atl, proj_b, x, out, nullptr, nullptr, Cch);
}

// round 10
// speedup vs baseline: 2.5335x; 1.0349x over previous
#include <cuda_runtime.h>
#include <cuda_bf16.h>
#include <cstdint>

// ---------------------------------------------------------------------------
// AttentionBlock: B=16, C=512, H=W=32 (L=1024), 32 groups, 8 heads (ch=64)
// GroupNorm(->bf16 hi/lo, transposed) -> mma.sync qkv GEMM (bf16 hi/lo out,
// q pre-scaled) -> mma.sync flash attention (cp.async pipelined, TQ=128)
// -> mma.sync proj GEMM + bias + residual -> fp32 out.
// All matmuls: split-bf16 (hi+lo), 3 MMAs ~ fp32 precision (m16n8k16).
// ---------------------------------------------------------------------------

#define Bsz  16
#define Cch  512
#define Lsp  1024
#define NH   8
#define CH   64
#define EPSV 1e-4f

__device__ __nv_bfloat16 g_xth[Bsz * Lsp * Cch];   // X^T hi [b][l][c]
__device__ __nv_bfloat16 g_xtl[Bsz * Lsp * Cch];   // X^T lo
__device__ __nv_bfloat16 g_qh [Bsz * 3*Cch * Lsp]; // qkv hi [b][3C][l] (q scaled)
__device__ __nv_bfloat16 g_ql [Bsz * 3*Cch * Lsp]; // qkv lo
__device__ __nv_bfloat16 g_ath[Bsz * Lsp * Cch];   // A^T hi [b][l][c]
__device__ __nv_bfloat16 g_atl[Bsz * Lsp * Cch];   // A^T lo
__device__ __nv_bfloat16 g_wqh[3*Cch * Cch];       // qkv_w hi [M,K]
__device__ __nv_bfloat16 g_wql[3*Cch * Cch];
__device__ __nv_bfloat16 g_wph[Cch * Cch];         // proj_w hi
__device__ __nv_bfloat16 g_wpl[Cch * Cch];

// ---------------------------------------------------------------------------
// PTX helpers
// ---------------------------------------------------------------------------
__device__ __forceinline__ uint32_t smem_to_u32(const void* p) {
    uint32_t a;
    asm("{ .reg .u64 t; cvta.to.shared.u64 t, %1; cvt.u32.u64 %0, t; }"
        : "=r"(a) : "l"(p));
    return a;
}
__device__ __forceinline__ void mma_bf16(float* d, const uint32_t* a, const uint32_t* b) {
    asm volatile(
        "mma.sync.aligned.m16n8k16.row.col.f32.bf16.bf16.f32 "
        "{%0,%1,%2,%3}, {%4,%5,%6,%7}, {%8,%9}, {%0,%1,%2,%3};\n"
        : "+f"(d[0]), "+f"(d[1]), "+f"(d[2]), "+f"(d[3])
        : "r"(a[0]), "r"(a[1]), "r"(a[2]), "r"(a[3]), "r"(b[0]), "r"(b[1]));
}
__device__ __forceinline__ void ldsm_x4(uint32_t* r, uint32_t addr) {
    asm volatile("ldmatrix.sync.aligned.m8n8.x4.shared.b16 {%0,%1,%2,%3}, [%4];"
        : "=r"(r[0]), "=r"(r[1]), "=r"(r[2]), "=r"(r[3]) : "r"(addr));
}
__device__ __forceinline__ void ldsm_x4_trans(uint32_t* r, uint32_t addr) {
    asm volatile("ldmatrix.sync.aligned.m8n8.x4.trans.shared.b16 {%0,%1,%2,%3}, [%4];"
        : "=r"(r[0]), "=r"(r[1]), "=r"(r[2]), "=r"(r[3]) : "r"(addr));
}
#define CP_ASYNC16(sm, gm) \
    asm volatile("cp.async.cg.shared.global [%0], [%1], 16;" :: "r"(sm), "l"(gm))
#define CP_COMMIT() asm volatile("cp.async.commit_group;" ::: "memory")
#define CP_WAIT1()  asm volatile("cp.async.wait_group 1;" ::: "memory")
#define CP_WAIT0()  asm volatile("cp.async.wait_group 0;" ::: "memory")

__device__ __forceinline__ void split2(float v0, float v1, uint32_t& hp, uint32_t& lp) {
    __nv_bfloat16 h0 = __float2bfloat16(v0);
    __nv_bfloat16 h1 = __float2bfloat16(v1);
    __nv_bfloat16 l0 = __float2bfloat16(v0 - __bfloat162float(h0));
    __nv_bfloat16 l1 = __float2bfloat16(v1 - __bfloat162float(h1));
    hp = (uint32_t)__bfloat16_as_ushort(h0) | ((uint32_t)__bfloat16_as_ushort(h1) << 16);
    lp = (uint32_t)__bfloat16_as_ushort(l0) | ((uint32_t)__bfloat16_as_ushort(l1) << 16);
}

// ---------------------------------------------------------------------------
// weight split fp32 -> bf16 hi/lo
// ---------------------------------------------------------------------------
__global__ __launch_bounds__(256) void wsplit_kernel(
    const float* __restrict__ in, __nv_bfloat16* __restrict__ hi,
    __nv_bfloat16* __restrict__ lo, int n4)
{
    int i = blockIdx.x * 256 + threadIdx.x;
    if (i >= n4) return;
    float4 v = ((const float4*)in)[i];
    uint32_t h0, l0, h1, l1;
    split2(v.x, v.y, h0, l0);
    split2(v.z, v.w, h1, l1);
    ((uint2*)hi)[i] = make_uint2(h0, h1);
    ((uint2*)lo)[i] = make_uint2(l0, l1);
}

// ---------------------------------------------------------------------------
// GroupNorm -> transposed bf16 hi/lo Xt[b][l][c]
// ---------------------------------------------------------------------------
#define SM8S 1028
__global__ __launch_bounds__(256) void gn_kernel(
    const float* __restrict__ x, const float* __restrict__ w,
    const float* __restrict__ bb,
    __nv_bfloat16* __restrict__ xth, __nv_bfloat16* __restrict__ xtl)
{
    int batch = blockIdx.x >> 5;
    int g     = blockIdx.x & 31;
    const size_t base = ((size_t)batch * Cch + (size_t)g * 16) * Lsp;
    const float* xp = x + base;

    float s = 0.f, s2 = 0.f;
    for (int i = threadIdx.x * 4; i < 16 * Lsp; i += 256 * 4) {
        float4 v = *(const float4*)(xp + i);
        s  += v.x + v.y + v.z + v.w;
        s2 += v.x*v.x + v.y*v.y + v.z*v.z + v.w*v.w;
    }
    #pragma unroll
    for (int o = 16; o; o >>= 1) {
        s  += __shfl_xor_sync(0xffffffffu, s,  o);
        s2 += __shfl_xor_sync(0xffffffffu, s2, o);
    }
    __shared__ float sA[8], sB[8];
    __shared__ float sm8[8 * SM8S];
    int warp = threadIdx.x >> 5, lane = threadIdx.x & 31;
    if (lane == 0) { sA[warp] = s; sB[warp] = s2; }
    __syncthreads();
    if (threadIdx.x == 0) {
        float S = 0.f, S2 = 0.f;
        #pragma unroll
        for (int i = 0; i < 8; i++) { S += sA[i]; S2 += sB[i]; }
        float mu  = S  * (1.f / (16.f * Lsp));
        float var = S2 * (1.f / (16.f * Lsp)) - mu * mu;
        sA[0] = mu;
        sB[0] = rsqrtf(var + EPSV);
    }
    __syncthreads();
    float mu = sA[0], rstd = sB[0];
    int tid = threadIdx.x;

    #pragma unroll
    for (int half = 0; half < 2; half++) {
        if (half) __syncthreads();
        for (int i = tid * 4; i < 8 * Lsp; i += 256 * 4) {
            int r = i >> 10, col = i & 1023;
            int c = g * 16 + half * 8 + r;
            float sw = w[c] * rstd;
            float sb = bb[c] - mu * sw;
            float4 v = *(const float4*)(xp + (size_t)(half * 8 + r) * Lsp + col);
            v.x = v.x * sw + sb; v.y = v.y * sw + sb;
            v.z = v.z * sw + sb; v.w = v.w * sw + sb;
            *(float4*)(&sm8[r * SM8S + col]) = v;
        }
        __syncthreads();
        for (int n = tid; n < Lsp; n += 256) {
            uint32_t hp[4], lp[4];
            #pragma unroll
            for (int c2 = 0; c2 < 4; c2++)
                split2(sm8[(2*c2) * SM8S + n], sm8[(2*c2+1) * SM8S + n], hp[c2], lp[c2]);
            size_t o = ((size_t)batch * Lsp + n) * Cch + g * 16 + half * 8;
            *(uint4*)(xth + o) = make_uint4(hp[0], hp[1], hp[2], hp[3]);
            *(uint4*)(xtl + o) = make_uint4(lp[0], lp[1], lp[2], lp[3]);
        }
    }
}

// ---------------------------------------------------------------------------
// split-bf16 GEMM via mma.sync. CTA 128x128, BK=32, cp.async double-buffered.
// 3-pass split ordering: 4 independent accs between dependent MMAs.
// ---------------------------------------------------------------------------
#define GPAD   40
#define GPLB   (128 * GPAD * 2)
#define GSTGB  (4 * GPLB)
#define GSMEM  (2 * GSTGB)

__global__ __launch_bounds__(256) void gemm_mma(
    const __nv_bfloat16* __restrict__ Wh, const __nv_bfloat16* __restrict__ Wl,
    const __nv_bfloat16* __restrict__ Xh, const __nv_bfloat16* __restrict__ Xl,
    const float* __restrict__ bias, const float* __restrict__ resid,
    float* __restrict__ C,
    __nv_bfloat16* __restrict__ Oh, __nv_bfloat16* __restrict__ Ol, int M)
{
    extern __shared__ char smem[];
    uint32_t sb = smem_to_u32(smem);
    int tid = threadIdx.x;
    int wid = tid >> 5, lane = tid & 31;
    int m0 = blockIdx.y << 7, n0 = blockIdx.x << 7, b = blockIdx.z;

    const __nv_bfloat16* gsrc[8];
    uint32_t soff[8];
    #pragma unroll
    for (int i = 0; i < 8; i++) {
        int c = i * 256 + tid;
        int plane = c >> 9, row = (c >> 2) & 127, kc = c & 3;
        const __nv_bfloat16* gp;
        if      (plane == 0) gp = Wh + (size_t)(m0 + row) * Cch;
        else if (plane == 1) gp = Wl + (size_t)(m0 + row) * Cch;
        else if (plane == 2) gp = Xh + ((size_t)b * Lsp + n0 + row) * Cch;
        else                 gp = Xl + ((size_t)b * Lsp + n0 + row) * Cch;
        gsrc[i] = gp + kc * 8;
        soff[i] = plane * GPLB + row * (GPAD * 2) + kc * 16;
    }

    #pragma unroll
    for (int i = 0; i < 8; i++) CP_ASYNC16(sb + soff[i], gsrc[i]);
    CP_COMMIT();

    int wm = wid >> 1, wn = wid & 1;
    float acc[2][8][4];
    #pragma unroll
    for (int mt = 0; mt < 2; mt++)
        #pragma unroll
        for (int nt = 0; nt < 8; nt++)
            #pragma unroll
            for (int q = 0; q < 4; q++) acc[mt][nt][q] = 0.f;

    #pragma unroll 1
    for (int s = 0; s < 16; s++) {
        if (s + 1 < 16) {
            int k0 = (s + 1) * 32;
            uint32_t nbuf = ((s + 1) & 1) * GSTGB;
            #pragma unroll
            for (int i = 0; i < 8; i++) CP_ASYNC16(sb + nbuf + soff[i], gsrc[i] + k0);
            CP_COMMIT();
            CP_WAIT1();
        } else {
            CP_WAIT0();
        }
        __syncthreads();

        uint32_t sbase = sb + (s & 1) * GSTGB;
        #pragma unroll
        for (int ks = 0; ks < 2; ks++) {
            uint32_t ah[2][4], al[2][4];
            #pragma unroll
            for (int mt = 0; mt < 2; mt++) {
                uint32_t ao = sbase +
                    ((wm * 32 + mt * 16 + (lane & 15)) * GPAD + ks * 16 + ((lane >> 4) << 3)) * 2;
                ldsm_x4(ah[mt], ao);
                ldsm_x4(al[mt], ao + GPLB);
            }
            #pragma unroll
            for (int ntp = 0; ntp < 4; ntp++) {
                uint32_t bo = sbase + 2 * GPLB +
                    ((wn * 64 + ntp * 16 + (lane & 7) + ((lane >> 4) << 3)) * GPAD
                     + ks * 16 + (((lane >> 3) & 1) << 3)) * 2;
                uint32_t bh[4], bl[4];
                ldsm_x4(bh, bo);
                ldsm_x4(bl, bo + GPLB);
                // 3 passes: 4 independent accs between dependent MMAs on same acc
                #pragma unroll
                for (int mt = 0; mt < 2; mt++)
                    #pragma unroll
                    for (int sub = 0; sub < 2; sub++)
                        mma_bf16(acc[mt][ntp*2+sub], ah[mt], bh + sub * 2);
                #pragma unroll
                for (int mt = 0; mt < 2; mt++)
                    #pragma unroll
                    for (int sub = 0; sub < 2; sub++)
                        mma_bf16(acc[mt][ntp*2+sub], ah[mt], bl + sub * 2);
                #pragma unroll
                for (int mt = 0; mt < 2; mt++)
                    #pragma unroll
                    for (int sub = 0; sub < 2; sub++)
                        mma_bf16(acc[mt][ntp*2+sub], al[mt], bh + sub * 2);
            }
        }
        __syncthreads();
    }

    #pragma unroll
    for (int mt = 0; mt < 2; mt++) {
        int r0 = m0 + wm * 32 + mt * 16 + (lane >> 2);
        #pragma unroll
        for (int half = 0; half < 2; half++) {
            int r = r0 + half * 8;
            float bz = bias[r];
            #pragma unroll
            for (int nt = 0; nt < 8; nt++) {
                int col = n0 + wn * 64 + nt * 8 + 2 * (lane & 3);
                float v0 = acc[mt][nt][half * 2 + 0] + bz;
                float v1 = acc[mt][nt][half * 2 + 1] + bz;
                if (C) {
                    size_t o = ((size_t)b * M + r) * Lsp + col;
                    float2 rv = *(const float2*)(resid + o);
                    *(float2*)(C + o) = make_float2(v0 + rv.x, v1 + rv.y);
                } else {
                    if (r < Cch) { v0 *= 0.125f; v1 *= 0.125f; }
                    uint32_t hp, lp;
                    split2(v0, v1, hp, lp);
                    size_t o = ((size_t)b * M + r) * Lsp + col;
                    *(uint32_t*)(Oh + o) = hp;
                    *(uint32_t*)(Ol + o) = lp;
                }
            }
        }
    }
}

// ---------------------------------------------------------------------------
// flash attention v2: TQ=128, 256 threads (8 warps x m16), cp.async
// double-buffered K/V, x4 ldmatrix B-fragments.
// SMEM: Qh/Ql [64 ch][136 t], then 2 stages x (Kh Kl Vh Vl)[64][72].
// ---------------------------------------------------------------------------
#define QPAD  136
#define QPLB  (64 * QPAD * 2)        // 17408
#define KPAD  72
#define KPLB  (64 * KPAD * 2)        // 9216
#define KVSTG (4 * KPLB)             // 36864
#define ASMEM (2 * QPLB + 2 * KVSTG) // 108544

__device__ __forceinline__ void kv_stage(
    uint32_t dst, const __nv_bfloat16* qh, const __nv_bfloat16* ql,
    size_t krow, size_t vrow, int s0, int tid)
{
    #pragma unroll
    for (int i = 0; i < 8; i++) {
        int c = i * 256 + tid;
        int plane = c >> 9, row = (c >> 3) & 63, cc = c & 7;
        size_t grow = (plane < 2 ? krow : vrow) + row;
        const __nv_bfloat16* src = ((plane & 1) ? ql : qh) + grow * Lsp + s0 + cc * 8;
        CP_ASYNC16(dst + plane * KPLB + row * (KPAD * 2) + cc * 16, src);
    }
}

__global__ __launch_bounds__(256) void attn_mma(
    const __nv_bfloat16* __restrict__ qh, const __nv_bfloat16* __restrict__ ql,
    __nv_bfloat16* __restrict__ ath, __nv_bfloat16* __restrict__ atl)
{
    extern __shared__ char smem[];
    uint32_t sb = smem_to_u32(smem);
    int tid = threadIdx.x;
    int wid = tid >> 5, lane = tid & 31;
    int bh = blockIdx.y;
    int batch = bh >> 3, h = bh & 7;
    int t0 = blockIdx.x << 7;

    size_t qrow = (size_t)batch * (3 * Cch) + h * CH;
    size_t krow = qrow + Cch;
    size_t vrow = qrow + 2 * Cch;
    uint32_t kvb = sb + 2 * QPLB;

    // stage Q (cp.async group), then KV stage 0
    #pragma unroll
    for (int i = 0; i < 8; i++) {
        int c = i * 256 + tid;
        int plane = c >> 10, row = (c >> 4) & 63, cc = c & 15;
        const __nv_bfloat16* src = (plane ? ql : qh) + (qrow + row) * Lsp + t0 + cc * 8;
        CP_ASYNC16(sb + plane * QPLB + row * (QPAD * 2) + cc * 16, src);
    }
    CP_COMMIT();
    kv_stage(kvb, qh, ql, krow, vrow, 0, tid);
    CP_COMMIT();
    CP_WAIT1();          // Q done (KV0 may still be in flight)
    __syncthreads();

    // Q fragments (A: m=t, k=ch), register-resident
    uint32_t aqh[4][4], aql[4][4];
    {
        int mbase = wid * 16;
        #pragma unroll
        for (int k = 0; k < 4; k++) {
            uint32_t ao = sb +
                ((k * 16 + ((lane >> 4) << 3) + (lane & 7)) * QPAD
                 + mbase + (((lane >> 3) & 1) << 3)) * 2;
            ldsm_x4_trans(aqh[k], ao);
            ldsm_x4_trans(aql[k], ao + QPLB);
        }
    }

    float Oacc[8][4];
    #pragma unroll
    for (int nt = 0; nt < 8; nt++)
        #pragma unroll
        for (int q = 0; q < 4; q++) Oacc[nt][q] = 0.f;
    float mrow0 = -INFINITY, mrow1 = -INFINITY, lrow0 = 0.f, lrow1 = 0.f;

    #pragma unroll 1
    for (int s = 0; s < 16; s++) {
        if (s + 1 < 16) {
            kv_stage(kvb + ((s + 1) & 1) * KVSTG, qh, ql, krow, vrow, (s + 1) * 64, tid);
            CP_COMMIT();
            CP_WAIT1();
        } else {
            CP_WAIT0();
        }
        __syncthreads();
        uint32_t kb = kvb + (s & 1) * KVSTG;

        // S = Q K^T (hh + hl + lh), x4 B loads cover 2 n-tiles each
        float S[8][4];
        #pragma unroll
        for (int nt = 0; nt < 8; nt++) { S[nt][0]=S[nt][1]=S[nt][2]=S[nt][3]=0.f; }
        #pragma unroll
        for (int k = 0; k < 4; k++) {
            #pragma unroll
            for (int np = 0; np < 4; np++) {
                uint32_t ko = kb +
                    ((k * 16 + (((lane >> 3) & 1) << 3) + (lane & 7)) * KPAD
                     + np * 16 + ((lane >> 4) << 3)) * 2;
                uint32_t bh4[4], bl4[4];
                ldsm_x4_trans(bh4, ko);
                ldsm_x4_trans(bl4, ko + KPLB);
                mma_bf16(S[np*2],   aqh[k], bh4);
                mma_bf16(S[np*2+1], aqh[k], bh4 + 2);
                mma_bf16(S[np*2],   aqh[k], bl4);
                mma_bf16(S[np*2+1], aqh[k], bl4 + 2);
                mma_bf16(S[np*2],   aql[k], bh4);
                mma_bf16(S[np*2+1], aql[k], bh4 + 2);
            }
        }

        // online softmax (row r = lane/4 -> c0,c1 ; r+8 -> c2,c3)
        float mx0 = -INFINITY, mx1 = -INFINITY;
        #pragma unroll
        for (int nt = 0; nt < 8; nt++) {
            mx0 = fmaxf(mx0, fmaxf(S[nt][0], S[nt][1]));
            mx1 = fmaxf(mx1, fmaxf(S[nt][2], S[nt][3]));
        }
        #pragma unroll
        for (int o = 1; o <= 2; o <<= 1) {
            mx0 = fmaxf(mx0, __shfl_xor_sync(0xffffffffu, mx0, o));
            mx1 = fmaxf(mx1, __shfl_xor_sync(0xffffffffu, mx1, o));
        }
        float mn0 = fmaxf(mrow0, mx0), mn1 = fmaxf(mrow1, mx1);
        float alpha0 = __expf(mrow0 - mn0), alpha1 = __expf(mrow1 - mn1);
        mrow0 = mn0; mrow1 = mn1;
        float sum0 = 0.f, sum1 = 0.f;
        #pragma unroll
        for (int nt = 0; nt < 8; nt++) {
            S[nt][0] = __expf(S[nt][0] - mn0); sum0 += S[nt][0];
            S[nt][1] = __expf(S[nt][1] - mn0); sum0 += S[nt][1];
            S[nt][2] = __expf(S[nt][2] - mn1); sum1 += S[nt][2];
            S[nt][3] = __expf(S[nt][3] - mn1); sum1 += S[nt][3];
        }
        #pragma unroll
        for (int o = 1; o <= 2; o <<= 1) {
            sum0 += __shfl_xor_sync(0xffffffffu, sum0, o);
            sum1 += __shfl_xor_sync(0xffffffffu, sum1, o);
        }
        lrow0 = lrow0 * alpha0 + sum0;
        lrow1 = lrow1 * alpha1 + sum1;

        // pack P -> A frags (hi/lo): step j covers s-dim k16 = S tiles 2j,2j+1
        uint32_t ph[4][4], pl[4][4];
        #pragma unroll
        for (int j = 0; j < 4; j++) {
            split2(S[2*j][0],   S[2*j][1],   ph[j][0], pl[j][0]);
            split2(S[2*j][2],   S[2*j][3],   ph[j][1], pl[j][1]);
            split2(S[2*j+1][0], S[2*j+1][1], ph[j][2], pl[j][2]);
            split2(S[2*j+1][2], S[2*j+1][3], ph[j][3], pl[j][3]);
        }

        #pragma unroll
        for (int nt = 0; nt < 8; nt++) {
            Oacc[nt][0] *= alpha0; Oacc[nt][1] *= alpha0;
            Oacc[nt][2] *= alpha1; Oacc[nt][3] *= alpha1;
        }

        // O += P V (hh + hl + lh), x4 non-trans V loads cover 2 n(ch)-tiles
        uint32_t vb = kb + 2 * KPLB;
        #pragma unroll
        for (int np = 0; np < 4; np++) {
            #pragma unroll
            for (int j = 0; j < 4; j++) {
                uint32_t vo = vb +
                    ((np * 16 + ((lane >> 4) << 3) + (lane & 7)) * KPAD
                     + j * 16 + (((lane >> 3) & 1) << 3)) * 2;
                uint32_t vh4[4], vl4[4];
                ldsm_x4(vh4, vo);
                ldsm_x4(vl4, vo + KPLB);
                mma_bf16(Oacc[np*2],   ph[j], vh4);
                mma_bf16(Oacc[np*2+1], ph[j], vh4 + 2);
                mma_bf16(Oacc[np*2],   ph[j], vl4);
                mma_bf16(Oacc[np*2+1], ph[j], vl4 + 2);
                mma_bf16(Oacc[np*2],   pl[j], vh4);
                mma_bf16(Oacc[np*2+1], pl[j], vh4 + 2);
            }
        }
        __syncthreads();
    }

    // epilogue: O /= l, split hi/lo, write transposed At[b][l][c]
    float inv0 = 1.f / lrow0, inv1 = 1.f / lrow1;
    int r0 = t0 + wid * 16 + (lane >> 2);
    int r1 = r0 + 8;
    #pragma unroll
    for (int nt = 0; nt < 8; nt++) {
        int col = h * CH + nt * 8 + 2 * (lane & 3);
        uint32_t hp, lp;
        split2(Oacc[nt][0] * inv0, Oacc[nt][1] * inv0, hp, lp);
        size_t o0 = ((size_t)batch * Lsp + r0) * Cch + col;
        *(uint32_t*)(ath + o0) = hp;
        *(uint32_t*)(atl + o0) = lp;
        split2(Oacc[nt][2] * inv1, Oacc[nt][3] * inv1, hp, lp);
        size_t o1 = ((size_t)batch * Lsp + r1) * Cch + col;
        *(uint32_t*)(ath + o1) = hp;
        *(uint32_t*)(atl + o1) = lp;
    }
}

// ---------------------------------------------------------------------------
// Launch
// ---------------------------------------------------------------------------
extern "C" void kernel_launch(void* const* d_in, const int* in_sizes, int n_in,
                              void* d_out, int out_size)
{
    const float* x      = (const float*)d_in[0];
    const float* norm_w = (const float*)d_in[1];
    const float* norm_b = (const float*)d_in[2];
    const float* qkv_w  = (const float*)d_in[3];
    const float* qkv_b  = (const float*)d_in[4];
    const float* proj_w = (const float*)d_in[5];
    const float* proj_b = (const float*)d_in[6];
    float* out = (float*)d_out;

    __nv_bfloat16 *xth, *xtl, *qh, *ql, *ath, *atl, *wqh, *wql, *wph, *wpl;
    cudaGetSymbolAddress((void**)&xth, g_xth);
    cudaGetSymbolAddress((void**)&xtl, g_xtl);
    cudaGetSymbolAddress((void**)&qh,  g_qh);
    cudaGetSymbolAddress((void**)&ql,  g_ql);
    cudaGetSymbolAddress((void**)&ath, g_ath);
    cudaGetSymbolAddress((void**)&atl, g_atl);
    cudaGetSymbolAddress((void**)&wqh, g_wqh);
    cudaGetSymbolAddress((void**)&wql, g_wql);
    cudaGetSymbolAddress((void**)&wph, g_wph);
    cudaGetSymbolAddress((void**)&wpl, g_wpl);

    cudaFuncSetAttribute(gemm_mma, cudaFuncAttributeMaxDynamicSharedMemorySize, GSMEM);
    cudaFuncSetAttribute(attn_mma, cudaFuncAttributeMaxDynamicSharedMemorySize, ASMEM);

    wsplit_kernel<<<(3*Cch*Cch/4 + 255)/256, 256>>>(qkv_w, wqh, wql, 3*Cch*Cch/4);
    wsplit_kernel<<<(Cch*Cch/4 + 255)/256, 256>>>(proj_w, wph, wpl, Cch*Cch/4);

    gn_kernel<<<Bsz * 32, 256>>>(x, norm_w, norm_b, xth, xtl);

    gemm_mma<<<dim3(Lsp/128, (3*Cch)/128, Bsz), 256, GSMEM>>>(
        wqh, wql, xth, xtl, qkv_b, nullptr, nullptr, qh, ql, 3*Cch);

    attn_mma<<<dim3(Lsp/128, Bsz*NH), 256, ASMEM>>>(qh, ql, ath, atl);

    gemm_mma<<<dim3(Lsp/128, Cch/128, Bsz), 256, GSMEM>>>(
        wph, wpl, ath, atl, proj_b, x, out, nullptr, nullptr, Cch);
}

// round 11
// speedup vs baseline: 2.5492x; 1.0062x over previous
#include <cuda_runtime.h>
#include <cuda_bf16.h>
#include <cstdint>

// ---------------------------------------------------------------------------
// AttentionBlock: B=16, C=512, H=W=32 (L=1024), 32 groups, 8 heads (ch=64)
// GroupNorm(->bf16 hi/lo, transposed) -> mma.sync qkv GEMM (bf16 hi/lo out,
// q pre-scaled incl. log2e) -> mma.sync flash attention (cp.async pipelined,
// TQ=128, exp2-domain softmax) -> mma.sync proj GEMM + bias + residual.
// All matmuls: split-bf16 (hi+lo), 3 MMAs ~ fp32 precision (m16n8k16).
// GEMM v2: CTA 128x256, warp tile 32x128 (amortize LDSM over more MMAs).
// ---------------------------------------------------------------------------

#define Bsz  16
#define Cch  512
#define Lsp  1024
#define NH   8
#define CH   64
#define EPSV 1e-4f

__device__ __nv_bfloat16 g_xth[Bsz * Lsp * Cch];   // X^T hi [b][l][c]
__device__ __nv_bfloat16 g_xtl[Bsz * Lsp * Cch];   // X^T lo
__device__ __nv_bfloat16 g_qh [Bsz * 3*Cch * Lsp]; // qkv hi [b][3C][l] (q scaled)
__device__ __nv_bfloat16 g_ql [Bsz * 3*Cch * Lsp]; // qkv lo
__device__ __nv_bfloat16 g_ath[Bsz * Lsp * Cch];   // A^T hi [b][l][c]
__device__ __nv_bfloat16 g_atl[Bsz * Lsp * Cch];   // A^T lo
__device__ __nv_bfloat16 g_wqh[3*Cch * Cch];       // qkv_w hi [M,K]
__device__ __nv_bfloat16 g_wql[3*Cch * Cch];
__device__ __nv_bfloat16 g_wph[Cch * Cch];         // proj_w hi
__device__ __nv_bfloat16 g_wpl[Cch * Cch];

// q pre-scale: ch^-0.5 (both sides folded) * log2(e) for exp2-domain softmax
#define QSCALE (0.125f * 1.44269504088896f)

// ---------------------------------------------------------------------------
// PTX helpers
// ---------------------------------------------------------------------------
__device__ __forceinline__ uint32_t smem_to_u32(const void* p) {
    uint32_t a;
    asm("{ .reg .u64 t; cvta.to.shared.u64 t, %1; cvt.u32.u64 %0, t; }"
        : "=r"(a) : "l"(p));
    return a;
}
__device__ __forceinline__ void mma_bf16(float* d, const uint32_t* a, const uint32_t* b) {
    asm volatile(
        "mma.sync.aligned.m16n8k16.row.col.f32.bf16.bf16.f32 "
        "{%0,%1,%2,%3}, {%4,%5,%6,%7}, {%8,%9}, {%0,%1,%2,%3};\n"
        : "+f"(d[0]), "+f"(d[1]), "+f"(d[2]), "+f"(d[3])
        : "r"(a[0]), "r"(a[1]), "r"(a[2]), "r"(a[3]), "r"(b[0]), "r"(b[1]));
}
__device__ __forceinline__ void ldsm_x4(uint32_t* r, uint32_t addr) {
    asm volatile("ldmatrix.sync.aligned.m8n8.x4.shared.b16 {%0,%1,%2,%3}, [%4];"
        : "=r"(r[0]), "=r"(r[1]), "=r"(r[2]), "=r"(r[3]) : "r"(addr));
}
__device__ __forceinline__ void ldsm_x4_trans(uint32_t* r, uint32_t addr) {
    asm volatile("ldmatrix.sync.aligned.m8n8.x4.trans.shared.b16 {%0,%1,%2,%3}, [%4];"
        : "=r"(r[0]), "=r"(r[1]), "=r"(r[2]), "=r"(r[3]) : "r"(addr));
}
#define CP_ASYNC16(sm, gm) \
    asm volatile("cp.async.cg.shared.global [%0], [%1], 16;" :: "r"(sm), "l"(gm))
#define CP_COMMIT() asm volatile("cp.async.commit_group;" ::: "memory")
#define CP_WAIT1()  asm volatile("cp.async.wait_group 1;" ::: "memory")
#define CP_WAIT0()  asm volatile("cp.async.wait_group 0;" ::: "memory")

__device__ __forceinline__ void split2(float v0, float v1, uint32_t& hp, uint32_t& lp) {
    __nv_bfloat16 h0 = __float2bfloat16(v0);
    __nv_bfloat16 h1 = __float2bfloat16(v1);
    __nv_bfloat16 l0 = __float2bfloat16(v0 - __bfloat162float(h0));
    __nv_bfloat16 l1 = __float2bfloat16(v1 - __bfloat162float(h1));
    hp = (uint32_t)__bfloat16_as_ushort(h0) | ((uint32_t)__bfloat16_as_ushort(h1) << 16);
    lp = (uint32_t)__bfloat16_as_ushort(l0) | ((uint32_t)__bfloat16_as_ushort(l1) << 16);
}

// ---------------------------------------------------------------------------
// weight split fp32 -> bf16 hi/lo
// ---------------------------------------------------------------------------
__global__ __launch_bounds__(256) void wsplit_kernel(
    const float* __restrict__ in, __nv_bfloat16* __restrict__ hi,
    __nv_bfloat16* __restrict__ lo, int n4)
{
    int i = blockIdx.x * 256 + threadIdx.x;
    if (i >= n4) return;
    float4 v = ((const float4*)in)[i];
    uint32_t h0, l0, h1, l1;
    split2(v.x, v.y, h0, l0);
    split2(v.z, v.w, h1, l1);
    ((uint2*)hi)[i] = make_uint2(h0, h1);
    ((uint2*)lo)[i] = make_uint2(l0, l1);
}

// ---------------------------------------------------------------------------
// GroupNorm -> transposed bf16 hi/lo Xt[b][l][c]
// ---------------------------------------------------------------------------
#define SM8S 1028
__global__ __launch_bounds__(256) void gn_kernel(
    const float* __restrict__ x, const float* __restrict__ w,
    const float* __restrict__ bb,
    __nv_bfloat16* __restrict__ xth, __nv_bfloat16* __restrict__ xtl)
{
    int batch = blockIdx.x >> 5;
    int g     = blockIdx.x & 31;
    const size_t base = ((size_t)batch * Cch + (size_t)g * 16) * Lsp;
    const float* xp = x + base;

    float s = 0.f, s2 = 0.f;
    for (int i = threadIdx.x * 4; i < 16 * Lsp; i += 256 * 4) {
        float4 v = *(const float4*)(xp + i);
        s  += v.x + v.y + v.z + v.w;
        s2 += v.x*v.x + v.y*v.y + v.z*v.z + v.w*v.w;
    }
    #pragma unroll
    for (int o = 16; o; o >>= 1) {
        s  += __shfl_xor_sync(0xffffffffu, s,  o);
        s2 += __shfl_xor_sync(0xffffffffu, s2, o);
    }
    __shared__ float sA[8], sB[8];
    __shared__ float sm8[8 * SM8S];
    int warp = threadIdx.x >> 5, lane = threadIdx.x & 31;
    if (lane == 0) { sA[warp] = s; sB[warp] = s2; }
    __syncthreads();
    if (threadIdx.x == 0) {
        float S = 0.f, S2 = 0.f;
        #pragma unroll
        for (int i = 0; i < 8; i++) { S += sA[i]; S2 += sB[i]; }
        float mu  = S  * (1.f / (16.f * Lsp));
        float var = S2 * (1.f / (16.f * Lsp)) - mu * mu;
        sA[0] = mu;
        sB[0] = rsqrtf(var + EPSV);
    }
    __syncthreads();
    float mu = sA[0], rstd = sB[0];
    int tid = threadIdx.x;

    #pragma unroll
    for (int half = 0; half < 2; half++) {
        if (half) __syncthreads();
        for (int i = tid * 4; i < 8 * Lsp; i += 256 * 4) {
            int r = i >> 10, col = i & 1023;
            int c = g * 16 + half * 8 + r;
            float sw = w[c] * rstd;
            float sb = bb[c] - mu * sw;
            float4 v = *(const float4*)(xp + (size_t)(half * 8 + r) * Lsp + col);
            v.x = v.x * sw + sb; v.y = v.y * sw + sb;
            v.z = v.z * sw + sb; v.w = v.w * sw + sb;
            *(float4*)(&sm8[r * SM8S + col]) = v;
        }
        __syncthreads();
        for (int n = tid; n < Lsp; n += 256) {
            uint32_t hp[4], lp[4];
            #pragma unroll
            for (int c2 = 0; c2 < 4; c2++)
                split2(sm8[(2*c2) * SM8S + n], sm8[(2*c2+1) * SM8S + n], hp[c2], lp[c2]);
            size_t o = ((size_t)batch * Lsp + n) * Cch + g * 16 + half * 8;
            *(uint4*)(xth + o) = make_uint4(hp[0], hp[1], hp[2], hp[3]);
            *(uint4*)(xtl + o) = make_uint4(lp[0], lp[1], lp[2], lp[3]);
        }
    }
}

// ---------------------------------------------------------------------------
// split-bf16 GEMM v2: CTA 128x256, BK=32, warp tile 32x128 (8 warps 4x2),
// cp.async double-buffered. 1 CTA/SM; big register tile amortizes LDSM.
// SMEM stage: Ah Al [128][40] then Bh Bl [256][40] (bf16, +8 pad).
// ---------------------------------------------------------------------------
#define GPADE  40                       // bf16 elems per row (32 + 8 pad)
#define GROWB  (GPADE * 2)              // 80 bytes per row
#define GAPLB  (128 * GROWB)            // A plane bytes = 10240
#define GBPLB  (256 * GROWB)            // B plane bytes = 20480
#define GSTGB  (2 * GAPLB + 2 * GBPLB)  // stage = 61440
#define GSMEM  (2 * GSTGB)              // 122880

__global__ __launch_bounds__(256, 1) void gemm_mma(
    const __nv_bfloat16* __restrict__ Wh, const __nv_bfloat16* __restrict__ Wl,
    const __nv_bfloat16* __restrict__ Xh, const __nv_bfloat16* __restrict__ Xl,
    const float* __restrict__ bias, const float* __restrict__ resid,
    float* __restrict__ C,
    __nv_bfloat16* __restrict__ Oh, __nv_bfloat16* __restrict__ Ol, int M)
{
    extern __shared__ char smem[];
    uint32_t sb = smem_to_u32(smem);
    int tid = threadIdx.x;
    int wid = tid >> 5, lane = tid & 31;
    int m0 = blockIdx.y << 7, n0 = blockIdx.x << 8, b = blockIdx.z;

    const __nv_bfloat16* Ahp = Wh + (size_t)m0 * Cch;
    const __nv_bfloat16* Alp = Wl + (size_t)m0 * Cch;
    const __nv_bfloat16* Bhp = Xh + ((size_t)b * Lsp + n0) * Cch;
    const __nv_bfloat16* Blp = Xl + ((size_t)b * Lsp + n0) * Cch;

    int lrow = tid >> 2;       // 0..63
    int lkc  = tid & 3;        // 0..3 (16B chunks across k32)

    // stage loader: 12 x 16B chunks per thread
    auto load_stage = [&](uint32_t dst, int k0) {
        #pragma unroll
        for (int i = 0; i < 4; i++) {          // A: plane = i>>1, rowoff = (i&1)*64
            int row = ((i & 1) << 6) + lrow;
            const __nv_bfloat16* gp = ((i >> 1) ? Alp : Ahp) + (size_t)row * Cch + k0 + lkc * 8;
            CP_ASYNC16(dst + (i >> 1) * GAPLB + row * GROWB + lkc * 16, gp);
        }
        #pragma unroll
        for (int j = 0; j < 8; j++) {          // B: plane = j>>2, rowoff = (j&3)*64
            int row = ((j & 3) << 6) + lrow;
            const __nv_bfloat16* gp = ((j >> 2) ? Blp : Bhp) + (size_t)row * Cch + k0 + lkc * 8;
            CP_ASYNC16(dst + 2 * GAPLB + (j >> 2) * GBPLB + row * GROWB + lkc * 16, gp);
        }
    };

    load_stage(sb, 0);
    CP_COMMIT();

    int wm = wid >> 1, wn = wid & 1;           // 4 x 2 warp grid
    float acc[2][16][4];
    #pragma unroll
    for (int mt = 0; mt < 2; mt++)
        #pragma unroll
        for (int nt = 0; nt < 16; nt++)
            #pragma unroll
            for (int q = 0; q < 4; q++) acc[mt][nt][q] = 0.f;

    #pragma unroll 1
    for (int s = 0; s < 16; s++) {
        if (s + 1 < 16) {
            load_stage(sb + ((s + 1) & 1) * GSTGB, (s + 1) * 32);
            CP_COMMIT();
            CP_WAIT1();
        } else {
            CP_WAIT0();
        }
        __syncthreads();

        uint32_t sbase = sb + (s & 1) * GSTGB;
        #pragma unroll
        for (int ks = 0; ks < 2; ks++) {
            uint32_t ah[2][4], al[2][4];
            #pragma unroll
            for (int mt = 0; mt < 2; mt++) {
                uint32_t ao = sbase +
                    (wm * 32 + mt * 16 + (lane & 15)) * GROWB
                    + (ks * 16 + ((lane >> 4) << 3)) * 2;
                ldsm_x4(ah[mt], ao);
                ldsm_x4(al[mt], ao + GAPLB);
            }
            #pragma unroll
            for (int ntp = 0; ntp < 8; ntp++) {
                uint32_t bo = sbase + 2 * GAPLB +
                    (wn * 128 + ntp * 16 + (lane & 7) + ((lane >> 4) << 3)) * GROWB
                    + (ks * 16 + (((lane >> 3) & 1) << 3)) * 2;
                uint32_t bh4[4], bl4[4];
                ldsm_x4(bh4, bo);
                ldsm_x4(bl4, bo + GBPLB);
                #pragma unroll
                for (int mt = 0; mt < 2; mt++)
                    #pragma unroll
                    for (int sub = 0; sub < 2; sub++)
                        mma_bf16(acc[mt][ntp*2+sub], ah[mt], bh4 + sub * 2);
                #pragma unroll
                for (int mt = 0; mt < 2; mt++)
                    #pragma unroll
                    for (int sub = 0; sub < 2; sub++)
                        mma_bf16(acc[mt][ntp*2+sub], ah[mt], bl4 + sub * 2);
                #pragma unroll
                for (int mt = 0; mt < 2; mt++)
                    #pragma unroll
                    for (int sub = 0; sub < 2; sub++)
                        mma_bf16(acc[mt][ntp*2+sub], al[mt], bh4 + sub * 2);
            }
        }
        __syncthreads();
    }

    #pragma unroll
    for (int mt = 0; mt < 2; mt++) {
        int r0 = m0 + wm * 32 + mt * 16 + (lane >> 2);
        #pragma unroll
        for (int half = 0; half < 2; half++) {
            int r = r0 + half * 8;
            float bz = bias[r];
            #pragma unroll
            for (int nt = 0; nt < 16; nt++) {
                int col = n0 + wn * 128 + nt * 8 + 2 * (lane & 3);
                float v0 = acc[mt][nt][half * 2 + 0] + bz;
                float v1 = acc[mt][nt][half * 2 + 1] + bz;
                if (C) {
                    size_t o = ((size_t)b * M + r) * Lsp + col;
                    float2 rv = *(const float2*)(resid + o);
                    *(float2*)(C + o) = make_float2(v0 + rv.x, v1 + rv.y);
                } else {
                    if (r < Cch) { v0 *= QSCALE; v1 *= QSCALE; }
                    uint32_t hp, lp;
                    split2(v0, v1, hp, lp);
                    size_t o = ((size_t)b * M + r) * Lsp + col;
                    *(uint32_t*)(Oh + o) = hp;
                    *(uint32_t*)(Ol + o) = lp;
                }
            }
        }
    }
}

// ---------------------------------------------------------------------------
// flash attention: TQ=128, 256 threads (8 warps x m16), cp.async
// double-buffered K/V, x4 ldmatrix, exp2-domain softmax (log2e folded into q).
// __launch_bounds__(256,2): target 2 CTAs/SM so softmax bubbles overlap MMAs.
// ---------------------------------------------------------------------------
#define QPAD  136
#define QPLB  (64 * QPAD * 2)        // 17408
#define KPAD  72
#define KPLB  (64 * KPAD * 2)        // 9216
#define KVSTG (4 * KPLB)             // 36864
#define ASMEM (2 * QPLB + 2 * KVSTG) // 108544

__device__ __forceinline__ void kv_stage(
    uint32_t dst, const __nv_bfloat16* qh, const __nv_bfloat16* ql,
    size_t krow, size_t vrow, int s0, int tid)
{
    #pragma unroll
    for (int i = 0; i < 8; i++) {
        int c = i * 256 + tid;
        int plane = c >> 9, row = (c >> 3) & 63, cc = c & 7;
        size_t grow = (plane < 2 ? krow : vrow) + row;
        const __nv_bfloat16* src = ((plane & 1) ? ql : qh) + grow * Lsp + s0 + cc * 8;
        CP_ASYNC16(dst + plane * KPLB + row * (KPAD * 2) + cc * 16, src);
    }
}

__global__ __launch_bounds__(256, 2) void attn_mma(
    const __nv_bfloat16* __restrict__ qh, const __nv_bfloat16* __restrict__ ql,
    __nv_bfloat16* __restrict__ ath, __nv_bfloat16* __restrict__ atl)
{
    extern __shared__ char smem[];
    uint32_t sb = smem_to_u32(smem);
    int tid = threadIdx.x;
    int wid = tid >> 5, lane = tid & 31;
    int bh = blockIdx.y;
    int batch = bh >> 3, h = bh & 7;
    int t0 = blockIdx.x << 7;

    size_t qrow = (size_t)batch * (3 * Cch) + h * CH;
    size_t krow = qrow + Cch;
    size_t vrow = qrow + 2 * Cch;
    uint32_t kvb = sb + 2 * QPLB;

    #pragma unroll
    for (int i = 0; i < 8; i++) {
        int c = i * 256 + tid;
        int plane = c >> 10, row = (c >> 4) & 63, cc = c & 15;
        const __nv_bfloat16* src = (plane ? ql : qh) + (qrow + row) * Lsp + t0 + cc * 8;
        CP_ASYNC16(sb + plane * QPLB + row * (QPAD * 2) + cc * 16, src);
    }
    CP_COMMIT();
    kv_stage(kvb, qh, ql, krow, vrow, 0, tid);
    CP_COMMIT();
    CP_WAIT1();
    __syncthreads();

    uint32_t aqh[4][4], aql[4][4];
    {
        int mbase = wid * 16;
        #pragma unroll
        for (int k = 0; k < 4; k++) {
            uint32_t ao = sb +
                ((k * 16 + ((lane >> 4) << 3) + (lane & 7)) * QPAD
                 + mbase + (((lane >> 3) & 1) << 3)) * 2;
            ldsm_x4_trans(aqh[k], ao);
            ldsm_x4_trans(aql[k], ao + QPLB);
        }
    }

    float Oacc[8][4];
    #pragma unroll
    for (int nt = 0; nt < 8; nt++)
        #pragma unroll
        for (int q = 0; q < 4; q++) Oacc[nt][q] = 0.f;
    float mrow0 = -INFINITY, mrow1 = -INFINITY, lrow0 = 0.f, lrow1 = 0.f;

    #pragma unroll 1
    for (int s = 0; s < 16; s++) {
        if (s + 1 < 16) {
            kv_stage(kvb + ((s + 1) & 1) * KVSTG, qh, ql, krow, vrow, (s + 1) * 64, tid);
            CP_COMMIT();
            CP_WAIT1();
        } else {
            CP_WAIT0();
        }
        __syncthreads();
        uint32_t kb = kvb + (s & 1) * KVSTG;

        // S = Q K^T (hh + hl + lh); logits already in log2 domain
        float S[8][4];
        #pragma unroll
        for (int nt = 0; nt < 8; nt++) { S[nt][0]=S[nt][1]=S[nt][2]=S[nt][3]=0.f; }
        #pragma unroll
        for (int k = 0; k < 4; k++) {
            #pragma unroll
            for (int np = 0; np < 4; np++) {
                uint32_t ko = kb +
                    ((k * 16 + (((lane >> 3) & 1) << 3) + (lane & 7)) * KPAD
                     + np * 16 + ((lane >> 4) << 3)) * 2;
                uint32_t bh4[4], bl4[4];
                ldsm_x4_trans(bh4, ko);
                ldsm_x4_trans(bl4, ko + KPLB);
                mma_bf16(S[np*2],   aqh[k], bh4);
                mma_bf16(S[np*2+1], aqh[k], bh4 + 2);
                mma_bf16(S[np*2],   aqh[k], bl4);
                mma_bf16(S[np*2+1], aqh[k], bl4 + 2);
                mma_bf16(S[np*2],   aql[k], bh4);
                mma_bf16(S[np*2+1], aql[k], bh4 + 2);
            }
        }

        float mx0 = -INFINITY, mx1 = -INFINITY;
        #pragma unroll
        for (int nt = 0; nt < 8; nt++) {
            mx0 = fmaxf(mx0, fmaxf(S[nt][0], S[nt][1]));
            mx1 = fmaxf(mx1, fmaxf(S[nt][2], S[nt][3]));
        }
        #pragma unroll
        for (int o = 1; o <= 2; o <<= 1) {
            mx0 = fmaxf(mx0, __shfl_xor_sync(0xffffffffu, mx0, o));
            mx1 = fmaxf(mx1, __shfl_xor_sync(0xffffffffu, mx1, o));
        }
        float mn0 = fmaxf(mrow0, mx0), mn1 = fmaxf(mrow1, mx1);
        float alpha0 = exp2f(mrow0 - mn0), alpha1 = exp2f(mrow1 - mn1);
        mrow0 = mn0; mrow1 = mn1;
        float sum0 = 0.f, sum1 = 0.f;
        #pragma unroll
        for (int nt = 0; nt < 8; nt++) {
            S[nt][0] = exp2f(S[nt][0] - mn0); sum0 += S[nt][0];
            S[nt][1] = exp2f(S[nt][1] - mn0); sum0 += S[nt][1];
            S[nt][2] = exp2f(S[nt][2] - mn1); sum1 += S[nt][2];
            S[nt][3] = exp2f(S[nt][3] - mn1); sum1 += S[nt][3];
        }
        #pragma unroll
        for (int o = 1; o <= 2; o <<= 1) {
            sum0 += __shfl_xor_sync(0xffffffffu, sum0, o);
            sum1 += __shfl_xor_sync(0xffffffffu, sum1, o);
        }
        lrow0 = lrow0 * alpha0 + sum0;
        lrow1 = lrow1 * alpha1 + sum1;

        uint32_t ph[4][4], pl[4][4];
        #pragma unroll
        for (int j = 0; j < 4; j++) {
            split2(S[2*j][0],   S[2*j][1],   ph[j][0], pl[j][0]);
            split2(S[2*j][2],   S[2*j][3],   ph[j][1], pl[j][1]);
            split2(S[2*j+1][0], S[2*j+1][1], ph[j][2], pl[j][2]);
            split2(S[2*j+1][2], S[2*j+1][3], ph[j][3], pl[j][3]);
        }

        #pragma unroll
        for (int nt = 0; nt < 8; nt++) {
            Oacc[nt][0] *= alpha0; Oacc[nt][1] *= alpha0;
            Oacc[nt][2] *= alpha1; Oacc[nt][3] *= alpha1;
        }

        uint32_t vb = kb + 2 * KPLB;
        #pragma unroll
        for (int np = 0; np < 4; np++) {
            #pragma unroll
            for (int j = 0; j < 4; j++) {
                uint32_t vo = vb +
                    ((np * 16 + ((lane >> 4) << 3) + (lane & 7)) * KPAD
                     + j * 16 + (((lane >> 3) & 1) << 3)) * 2;
                uint32_t vh4[4], vl4[4];
                ldsm_x4(vh4, vo);
                ldsm_x4(vl4, vo + KPLB);
                mma_bf16(Oacc[np*2],   ph[j], vh4);
                mma_bf16(Oacc[np*2+1], ph[j], vh4 + 2);
                mma_bf16(Oacc[np*2],   ph[j], vl4);
                mma_bf16(Oacc[np*2+1], ph[j], vl4 + 2);
                mma_bf16(Oacc[np*2],   pl[j], vh4);
                mma_bf16(Oacc[np*2+1], pl[j], vh4 + 2);
            }
        }
        __syncthreads();
    }

    float inv0 = 1.f / lrow0, inv1 = 1.f / lrow1;
    int r0 = t0 + wid * 16 + (lane >> 2);
    int r1 = r0 + 8;
    #pragma unroll
    for (int nt = 0; nt < 8; nt++) {
        int col = h * CH + nt * 8 + 2 * (lane & 3);
        uint32_t hp, lp;
        split2(Oacc[nt][0] * inv0, Oacc[nt][1] * inv0, hp, lp);
        size_t o0 = ((size_t)batch * Lsp + r0) * Cch + col;
        *(uint32_t*)(ath + o0) = hp;
        *(uint32_t*)(atl + o0) = lp;
        split2(Oacc[nt][2] * inv1, Oacc[nt][3] * inv1, hp, lp);
        size_t o1 = ((size_t)batch * Lsp + r1) * Cch + col;
        *(uint32_t*)(ath + o1) = hp;
        *(uint32_t*)(atl + o1) = lp;
    }
}

// ---------------------------------------------------------------------------
// Launch
// ---------------------------------------------------------------------------
extern "C" void kernel_launch(void* const* d_in, const int* in_sizes, int n_in,
                              void* d_out, int out_size)
{
    const float* x      = (const float*)d_in[0];
    const float* norm_w = (const float*)d_in[1];
    const float* norm_b = (const float*)d_in[2];
    const float* qkv_w  = (const float*)d_in[3];
    const float* qkv_b  = (const float*)d_in[4];
    const float* proj_w = (const float*)d_in[5];
    const float* proj_b = (const float*)d_in[6];
    float* out = (float*)d_out;

    __nv_bfloat16 *xth, *xtl, *qh, *ql, *ath, *atl, *wqh, *wql, *wph, *wpl;
    cudaGetSymbolAddress((void**)&xth, g_xth);
    cudaGetSymbolAddress((void**)&xtl, g_xtl);
    cudaGetSymbolAddress((void**)&qh,  g_qh);
    cudaGetSymbolAddress((void**)&ql,  g_ql);
    cudaGetSymbolAddress((void**)&ath, g_ath);
    cudaGetSymbolAddress((void**)&atl, g_atl);
    cudaGetSymbolAddress((void**)&wqh, g_wqh);
    cudaGetSymbolAddress((void**)&wql, g_wql);
    cudaGetSymbolAddress((void**)&wph, g_wph);
    cudaGetSymbolAddress((void**)&wpl, g_wpl);

    cudaFuncSetAttribute(gemm_mma, cudaFuncAttributeMaxDynamicSharedMemorySize, GSMEM);
    cudaFuncSetAttribute(attn_mma, cudaFuncAttributeMaxDynamicSharedMemorySize, ASMEM);

    wsplit_kernel<<<(3*Cch*Cch/4 + 255)/256, 256>>>(qkv_w, wqh, wql, 3*Cch*Cch/4);
    wsplit_kernel<<<(Cch*Cch/4 + 255)/256, 256>>>(proj_w, wph, wpl, Cch*Cch/4);

    gn_kernel<<<Bsz * 32, 256>>>(x, norm_w, norm_b, xth, xtl);

    // qkv: [1536,512] @ [512,1024] per batch, N-tiles of 256
    gemm_mma<<<dim3(Lsp/256, (3*Cch)/128, Bsz), 256, GSMEM>>>(
        wqh, wql, xth, xtl, qkv_b, nullptr, nullptr, qh, ql, 3*Cch);

    attn_mma<<<dim3(Lsp/128, Bsz*NH), 256, ASMEM>>>(qh, ql, ath, atl);

    // proj: [512,512] @ [512,1024] per batch + bias + residual
    gemm_mma<<<dim3(Lsp/256, Cch/128, Bsz), 256, GSMEM>>>(
        wph, wpl, ath, atl, proj_b, x, out, nullptr, nullptr, Cch);
}

// round 13
// speedup vs baseline: 2.9698x; 1.1650x over previous
#include <cuda_runtime.h>
#include <cuda_bf16.h>
#include <cstdint>

// ---------------------------------------------------------------------------
// AttentionBlock: B=16, C=512, H=W=32 (L=1024), 32 groups, 8 heads (ch=64)
// GroupNorm(->bf16 hi/lo, transposed) -> mma.sync qkv GEMM (bf16 hi/lo out,
// q pre-scaled incl. log2e) -> mma.sync flash attention (cp.async pipelined,
// TQ=128, exp2-domain softmax, 2 CTAs/SM) -> mma.sync proj GEMM + residual.
// All matmuls: split-bf16 (hi+lo), 3 MMAs ~ fp32 precision (m16n8k16).
// GEMM v3b: CTA 128x128 (2 CTAs/SM), BK=32, 3-stage cp.async ring with
// single __syncthreads per stage; 64B rows + XOR chunk swizzle
// (16B-aligned cp.async, conflict-free ldmatrix, no padding).
// ---------------------------------------------------------------------------

#define Bsz  16
#define Cch  512
#define Lsp  1024
#define NH   8
#define CH   64
#define EPSV 1e-4f

__device__ __nv_bfloat16 g_xth[Bsz * Lsp * Cch];   // X^T hi [b][l][c]
__device__ __nv_bfloat16 g_xtl[Bsz * Lsp * Cch];   // X^T lo
__device__ __nv_bfloat16 g_qh [Bsz * 3*Cch * Lsp]; // qkv hi [b][3C][l] (q scaled)
__device__ __nv_bfloat16 g_ql [Bsz * 3*Cch * Lsp]; // qkv lo
__device__ __nv_bfloat16 g_ath[Bsz * Lsp * Cch];   // A^T hi [b][l][c]
__device__ __nv_bfloat16 g_atl[Bsz * Lsp * Cch];   // A^T lo
__device__ __nv_bfloat16 g_wqh[3*Cch * Cch];       // qkv_w hi [M,K]
__device__ __nv_bfloat16 g_wql[3*Cch * Cch];
__device__ __nv_bfloat16 g_wph[Cch * Cch];         // proj_w hi
__device__ __nv_bfloat16 g_wpl[Cch * Cch];

// q pre-scale: ch^-0.5 (both sides folded) * log2(e) for exp2-domain softmax
#define QSCALE (0.125f * 1.44269504088896f)

// ---------------------------------------------------------------------------
// PTX helpers
// ---------------------------------------------------------------------------
__device__ __forceinline__ uint32_t smem_to_u32(const void* p) {
    uint32_t a;
    asm("{ .reg .u64 t; cvta.to.shared.u64 t, %1; cvt.u32.u64 %0, t; }"
        : "=r"(a) : "l"(p));
    return a;
}
__device__ __forceinline__ void mma_bf16(float* d, const uint32_t* a, const uint32_t* b) {
    asm volatile(
        "mma.sync.aligned.m16n8k16.row.col.f32.bf16.bf16.f32 "
        "{%0,%1,%2,%3}, {%4,%5,%6,%7}, {%8,%9}, {%0,%1,%2,%3};\n"
        : "+f"(d[0]), "+f"(d[1]), "+f"(d[2]), "+f"(d[3])
        : "r"(a[0]), "r"(a[1]), "r"(a[2]), "r"(a[3]), "r"(b[0]), "r"(b[1]));
}
__device__ __forceinline__ void ldsm_x4(uint32_t* r, uint32_t addr) {
    asm volatile("ldmatrix.sync.aligned.m8n8.x4.shared.b16 {%0,%1,%2,%3}, [%4];"
        : "=r"(r[0]), "=r"(r[1]), "=r"(r[2]), "=r"(r[3]) : "r"(addr));
}
__device__ __forceinline__ void ldsm_x4_trans(uint32_t* r, uint32_t addr) {
    asm volatile("ldmatrix.sync.aligned.m8n8.x4.trans.shared.b16 {%0,%1,%2,%3}, [%4];"
        : "=r"(r[0]), "=r"(r[1]), "=r"(r[2]), "=r"(r[3]) : "r"(addr));
}
#define CP_ASYNC16(sm, gm) \
    asm volatile("cp.async.cg.shared.global [%0], [%1], 16;" :: "r"(sm), "l"(gm))
#define CP_COMMIT() asm volatile("cp.async.commit_group;" ::: "memory")
#define CP_WAIT1()  asm volatile("cp.async.wait_group 1;" ::: "memory")
#define CP_WAIT0()  asm volatile("cp.async.wait_group 0;" ::: "memory")

__device__ __forceinline__ void split2(float v0, float v1, uint32_t& hp, uint32_t& lp) {
    __nv_bfloat16 h0 = __float2bfloat16(v0);
    __nv_bfloat16 h1 = __float2bfloat16(v1);
    __nv_bfloat16 l0 = __float2bfloat16(v0 - __bfloat162float(h0));
    __nv_bfloat16 l1 = __float2bfloat16(v1 - __bfloat162float(h1));
    hp = (uint32_t)__bfloat16_as_ushort(h0) | ((uint32_t)__bfloat16_as_ushort(h1) << 16);
    lp = (uint32_t)__bfloat16_as_ushort(l0) | ((uint32_t)__bfloat16_as_ushort(l1) << 16);
}

// ---------------------------------------------------------------------------
// weight split fp32 -> bf16 hi/lo
// ---------------------------------------------------------------------------
__global__ __launch_bounds__(256) void wsplit_kernel(
    const float* __restrict__ in, __nv_bfloat16* __restrict__ hi,
    __nv_bfloat16* __restrict__ lo, int n4)
{
    int i = blockIdx.x * 256 + threadIdx.x;
    if (i >= n4) return;
    float4 v = ((const float4*)in)[i];
    uint32_t h0, l0, h1, l1;
    split2(v.x, v.y, h0, l0);
    split2(v.z, v.w, h1, l1);
    ((uint2*)hi)[i] = make_uint2(h0, h1);
    ((uint2*)lo)[i] = make_uint2(l0, l1);
}

// ---------------------------------------------------------------------------
// GroupNorm -> transposed bf16 hi/lo Xt[b][l][c]
// ---------------------------------------------------------------------------
#define SM8S 1028
__global__ __launch_bounds__(256) void gn_kernel(
    const float* __restrict__ x, const float* __restrict__ w,
    const float* __restrict__ bb,
    __nv_bfloat16* __restrict__ xth, __nv_bfloat16* __restrict__ xtl)
{
    int batch = blockIdx.x >> 5;
    int g     = blockIdx.x & 31;
    const size_t base = ((size_t)batch * Cch + (size_t)g * 16) * Lsp;
    const float* xp = x + base;

    float s = 0.f, s2 = 0.f;
    for (int i = threadIdx.x * 4; i < 16 * Lsp; i += 256 * 4) {
        float4 v = *(const float4*)(xp + i);
        s  += v.x + v.y + v.z + v.w;
        s2 += v.x*v.x + v.y*v.y + v.z*v.z + v.w*v.w;
    }
    #pragma unroll
    for (int o = 16; o; o >>= 1) {
        s  += __shfl_xor_sync(0xffffffffu, s,  o);
        s2 += __shfl_xor_sync(0xffffffffu, s2, o);
    }
    __shared__ float sA[8], sB[8];
    __shared__ float sm8[8 * SM8S];
    int warp = threadIdx.x >> 5, lane = threadIdx.x & 31;
    if (lane == 0) { sA[warp] = s; sB[warp] = s2; }
    __syncthreads();
    if (threadIdx.x == 0) {
        float S = 0.f, S2 = 0.f;
        #pragma unroll
        for (int i = 0; i < 8; i++) { S += sA[i]; S2 += sB[i]; }
        float mu  = S  * (1.f / (16.f * Lsp));
        float var = S2 * (1.f / (16.f * Lsp)) - mu * mu;
        sA[0] = mu;
        sB[0] = rsqrtf(var + EPSV);
    }
    __syncthreads();
    float mu = sA[0], rstd = sB[0];
    int tid = threadIdx.x;

    #pragma unroll
    for (int half = 0; half < 2; half++) {
        if (half) __syncthreads();
        for (int i = tid * 4; i < 8 * Lsp; i += 256 * 4) {
            int r = i >> 10, col = i & 1023;
            int c = g * 16 + half * 8 + r;
            float sw = w[c] * rstd;
            float sb = bb[c] - mu * sw;
            float4 v = *(const float4*)(xp + (size_t)(half * 8 + r) * Lsp + col);
            v.x = v.x * sw + sb; v.y = v.y * sw + sb;
            v.z = v.z * sw + sb; v.w = v.w * sw + sb;
            *(float4*)(&sm8[r * SM8S + col]) = v;
        }
        __syncthreads();
        for (int n = tid; n < Lsp; n += 256) {
            uint32_t hp[4], lp[4];
            #pragma unroll
            for (int c2 = 0; c2 < 4; c2++)
                split2(sm8[(2*c2) * SM8S + n], sm8[(2*c2+1) * SM8S + n], hp[c2], lp[c2]);
            size_t o = ((size_t)batch * Lsp + n) * Cch + g * 16 + half * 8;
            *(uint4*)(xth + o) = make_uint4(hp[0], hp[1], hp[2], hp[3]);
            *(uint4*)(xtl + o) = make_uint4(lp[0], lp[1], lp[2], lp[3]);
        }
    }
}

// ---------------------------------------------------------------------------
// split-bf16 GEMM v3b: CTA 128x128, BK=32, warp tile 32x64 (8 warps 4x2),
// 3-stage cp.async ring, 64B rows + XOR chunk swizzle, one barrier/stage,
// 2 CTAs/SM.
// Swizzle: 16B chunk kc of row r stored at chunk slot kc ^ ((r>>1)&3).
// ---------------------------------------------------------------------------
#define GROWB  64                        // 64B data per row, no pad
#define GPLB   (128 * GROWB)             // plane bytes = 8192
#define GSTGB  (4 * GPLB)                // stage bytes = 32768
#define GSMEM  (3 * GSTGB)               // 98304

__global__ __launch_bounds__(256, 2) void gemm_mma(
    const __nv_bfloat16* __restrict__ Wh, const __nv_bfloat16* __restrict__ Wl,
    const __nv_bfloat16* __restrict__ Xh, const __nv_bfloat16* __restrict__ Xl,
    const float* __restrict__ bias, const float* __restrict__ resid,
    float* __restrict__ C,
    __nv_bfloat16* __restrict__ Oh, __nv_bfloat16* __restrict__ Ol, int M)
{
    extern __shared__ char smem[];
    uint32_t sb = smem_to_u32(smem);
    int tid = threadIdx.x;
    int wid = tid >> 5, lane = tid & 31;
    int m0 = blockIdx.y << 7, n0 = blockIdx.x << 7, b = blockIdx.z;

    // per-thread load slots: 8 chunks of 16B per stage, swizzled dst
    const __nv_bfloat16* gsrc[8];
    uint32_t soff[8];
    #pragma unroll
    for (int i = 0; i < 8; i++) {
        int c = i * 256 + tid;
        int plane = c >> 9, row = (c >> 2) & 127, kc = c & 3;
        const __nv_bfloat16* gp;
        if      (plane == 0) gp = Wh + (size_t)(m0 + row) * Cch;
        else if (plane == 1) gp = Wl + (size_t)(m0 + row) * Cch;
        else if (plane == 2) gp = Xh + ((size_t)b * Lsp + n0 + row) * Cch;
        else                 gp = Xl + ((size_t)b * Lsp + n0 + row) * Cch;
        gsrc[i] = gp + kc * 8;
        soff[i] = plane * GPLB + row * GROWB + ((kc ^ ((row >> 1) & 3)) << 4);
    }

    // prologue: stages 0 and 1
    #pragma unroll
    for (int i = 0; i < 8; i++) CP_ASYNC16(sb + soff[i], gsrc[i]);
    CP_COMMIT();
    #pragma unroll
    for (int i = 0; i < 8; i++) CP_ASYNC16(sb + GSTGB + soff[i], gsrc[i] + 32);
    CP_COMMIT();

    int wm = wid >> 1, wn = wid & 1;
    float acc[2][8][4];
    #pragma unroll
    for (int mt = 0; mt < 2; mt++)
        #pragma unroll
        for (int nt = 0; nt < 8; nt++)
            #pragma unroll
            for (int q = 0; q < 4; q++) acc[mt][nt][q] = 0.f;

    // precompute swizzled ldmatrix addresses (relative to stage base)
    // A: rows wm*32+mt*16+(lane&15), chunk = ks*2 + (lane>>4)
    uint32_t aoff[2][2], boff[2][4];
    #pragma unroll
    for (int ks = 0; ks < 2; ks++) {
        #pragma unroll
        for (int mt = 0; mt < 2; mt++) {
            int r = wm * 32 + mt * 16 + (lane & 15);
            int ck = ks * 2 + (lane >> 4);
            aoff[ks][mt] = r * GROWB + ((ck ^ ((r >> 1) & 3)) << 4);
        }
        #pragma unroll
        for (int ntp = 0; ntp < 4; ntp++) {
            int r = wn * 64 + ntp * 16 + (lane & 7) + ((lane >> 4) << 3);
            int ck = ks * 2 + ((lane >> 3) & 1);
            boff[ks][ntp] = 2 * GPLB + r * GROWB + ((ck ^ ((r >> 1) & 3)) << 4);
        }
    }

    int buf = 0;                 // s % 3
    int pbuf = 2;                // (s+2) % 3
    #pragma unroll 1
    for (int s = 0; s < 16; s++) {
        CP_WAIT1();              // stage s's group complete (s+1 may be pending)
        __syncthreads();         // all warps done reading stage s-1 (buf pbuf)
        if (s + 2 < 16) {
            int k0 = (s + 2) * 32;
            uint32_t nb = (uint32_t)pbuf * GSTGB;
            #pragma unroll
            for (int i = 0; i < 8; i++) CP_ASYNC16(sb + nb + soff[i], gsrc[i] + k0);
        }
        CP_COMMIT();             // (possibly empty) group keeps wait count uniform

        uint32_t sbase = sb + (uint32_t)buf * GSTGB;
        #pragma unroll
        for (int ks = 0; ks < 2; ks++) {
            uint32_t ah[2][4], al[2][4];
            #pragma unroll
            for (int mt = 0; mt < 2; mt++) {
                uint32_t ao = sbase + aoff[ks][mt];
                ldsm_x4(ah[mt], ao);
                ldsm_x4(al[mt], ao + GPLB);
            }
            #pragma unroll
            for (int ntp = 0; ntp < 4; ntp++) {
                uint32_t bo = sbase + boff[ks][ntp];
                uint32_t bh4[4], bl4[4];
                ldsm_x4(bh4, bo);
                ldsm_x4(bl4, bo + GPLB);
                #pragma unroll
                for (int mt = 0; mt < 2; mt++)
                    #pragma unroll
                    for (int sub = 0; sub < 2; sub++)
                        mma_bf16(acc[mt][ntp*2+sub], ah[mt], bh4 + sub * 2);
                #pragma unroll
                for (int mt = 0; mt < 2; mt++)
                    #pragma unroll
                    for (int sub = 0; sub < 2; sub++)
                        mma_bf16(acc[mt][ntp*2+sub], ah[mt], bl4 + sub * 2);
                #pragma unroll
                for (int mt = 0; mt < 2; mt++)
                    #pragma unroll
                    for (int sub = 0; sub < 2; sub++)
                        mma_bf16(acc[mt][ntp*2+sub], al[mt], bh4 + sub * 2);
            }
        }
        buf  = (buf  == 2) ? 0 : buf  + 1;
        pbuf = (pbuf == 2) ? 0 : pbuf + 1;
    }

    #pragma unroll
    for (int mt = 0; mt < 2; mt++) {
        int r0 = m0 + wm * 32 + mt * 16 + (lane >> 2);
        #pragma unroll
        for (int half = 0; half < 2; half++) {
            int r = r0 + half * 8;
            float bz = bias[r];
            #pragma unroll
            for (int nt = 0; nt < 8; nt++) {
                int col = n0 + wn * 64 + nt * 8 + 2 * (lane & 3);
                float v0 = acc[mt][nt][half * 2 + 0] + bz;
                float v1 = acc[mt][nt][half * 2 + 1] + bz;
                if (C) {
                    size_t o = ((size_t)b * M + r) * Lsp + col;
                    float2 rv = *(const float2*)(resid + o);
                    *(float2*)(C + o) = make_float2(v0 + rv.x, v1 + rv.y);
                } else {
                    if (r < Cch) { v0 *= QSCALE; v1 *= QSCALE; }
                    uint32_t hp, lp;
                    split2(v0, v1, hp, lp);
                    size_t o = ((size_t)b * M + r) * Lsp + col;
                    *(uint32_t*)(Oh + o) = hp;
                    *(uint32_t*)(Ol + o) = lp;
                }
            }
        }
    }
}

// ---------------------------------------------------------------------------
// flash attention: TQ=128, 256 threads (8 warps x m16), cp.async
// double-buffered K/V, x4 ldmatrix, exp2-domain softmax, 2 CTAs/SM.
// (unchanged from R11 passing version)
// ---------------------------------------------------------------------------
#define QPAD  136
#define QPLB  (64 * QPAD * 2)        // 17408
#define KPAD  72
#define KPLB  (64 * KPAD * 2)        // 9216
#define KVSTG (4 * KPLB)             // 36864
#define ASMEM (2 * QPLB + 2 * KVSTG) // 108544

__device__ __forceinline__ void kv_stage(
    uint32_t dst, const __nv_bfloat16* qh, const __nv_bfloat16* ql,
    size_t krow, size_t vrow, int s0, int tid)
{
    #pragma unroll
    for (int i = 0; i < 8; i++) {
        int c = i * 256 + tid;
        int plane = c >> 9, row = (c >> 3) & 63, cc = c & 7;
        size_t grow = (plane < 2 ? krow : vrow) + row;
        const __nv_bfloat16* src = ((plane & 1) ? ql : qh) + grow * Lsp + s0 + cc * 8;
        CP_ASYNC16(dst + plane * KPLB + row * (KPAD * 2) + cc * 16, src);
    }
}

__global__ __launch_bounds__(256, 2) void attn_mma(
    const __nv_bfloat16* __restrict__ qh, const __nv_bfloat16* __restrict__ ql,
    __nv_bfloat16* __restrict__ ath, __nv_bfloat16* __restrict__ atl)
{
    extern __shared__ char smem[];
    uint32_t sb = smem_to_u32(smem);
    int tid = threadIdx.x;
    int wid = tid >> 5, lane = tid & 31;
    int bh = blockIdx.y;
    int batch = bh >> 3, h = bh & 7;
    int t0 = blockIdx.x << 7;

    size_t qrow = (size_t)batch * (3 * Cch) + h * CH;
    size_t krow = qrow + Cch;
    size_t vrow = qrow + 2 * Cch;
    uint32_t kvb = sb + 2 * QPLB;

    #pragma unroll
    for (int i = 0; i < 8; i++) {
        int c = i * 256 + tid;
        int plane = c >> 10, row = (c >> 4) & 63, cc = c & 15;
        const __nv_bfloat16* src = (plane ? ql : qh) + (qrow + row) * Lsp + t0 + cc * 8;
        CP_ASYNC16(sb + plane * QPLB + row * (QPAD * 2) + cc * 16, src);
    }
    CP_COMMIT();
    kv_stage(kvb, qh, ql, krow, vrow, 0, tid);
    CP_COMMIT();
    CP_WAIT1();
    __syncthreads();

    uint32_t aqh[4][4], aql[4][4];
    {
        int mbase = wid * 16;
        #pragma unroll
        for (int k = 0; k < 4; k++) {
            uint32_t ao = sb +
                ((k * 16 + ((lane >> 4) << 3) + (lane & 7)) * QPAD
                 + mbase + (((lane >> 3) & 1) << 3)) * 2;
            ldsm_x4_trans(aqh[k], ao);
            ldsm_x4_trans(aql[k], ao + QPLB);
        }
    }

    float Oacc[8][4];
    #pragma unroll
    for (int nt = 0; nt < 8; nt++)
        #pragma unroll
        for (int q = 0; q < 4; q++) Oacc[nt][q] = 0.f;
    float mrow0 = -INFINITY, mrow1 = -INFINITY, lrow0 = 0.f, lrow1 = 0.f;

    #pragma unroll 1
    for (int s = 0; s < 16; s++) {
        if (s + 1 < 16) {
            kv_stage(kvb + ((s + 1) & 1) * KVSTG, qh, ql, krow, vrow, (s + 1) * 64, tid);
            CP_COMMIT();
            CP_WAIT1();
        } else {
            CP_WAIT0();
        }
        __syncthreads();
        uint32_t kb = kvb + (s & 1) * KVSTG;

        // S = Q K^T (hh + hl + lh); logits already in log2 domain
        float S[8][4];
        #pragma unroll
        for (int nt = 0; nt < 8; nt++) { S[nt][0]=S[nt][1]=S[nt][2]=S[nt][3]=0.f; }
        #pragma unroll
        for (int k = 0; k < 4; k++) {
            #pragma unroll
            for (int np = 0; np < 4; np++) {
                uint32_t ko = kb +
                    ((k * 16 + (((lane >> 3) & 1) << 3) + (lane & 7)) * KPAD
                     + np * 16 + ((lane >> 4) << 3)) * 2;
                uint32_t bh4[4], bl4[4];
                ldsm_x4_trans(bh4, ko);
                ldsm_x4_trans(bl4, ko + KPLB);
                mma_bf16(S[np*2],   aqh[k], bh4);
                mma_bf16(S[np*2+1], aqh[k], bh4 + 2);
                mma_bf16(S[np*2],   aqh[k], bl4);
                mma_bf16(S[np*2+1], aqh[k], bl4 + 2);
                mma_bf16(S[np*2],   aql[k], bh4);
                mma_bf16(S[np*2+1], aql[k], bh4 + 2);
            }
        }

        float mx0 = -INFINITY, mx1 = -INFINITY;
        #pragma unroll
        for (int nt = 0; nt < 8; nt++) {
            mx0 = fmaxf(mx0, fmaxf(S[nt][0], S[nt][1]));
            mx1 = fmaxf(mx1, fmaxf(S[nt][2], S[nt][3]));
        }
        #pragma unroll
        for (int o = 1; o <= 2; o <<= 1) {
            mx0 = fmaxf(mx0, __shfl_xor_sync(0xffffffffu, mx0, o));
            mx1 = fmaxf(mx1, __shfl_xor_sync(0xffffffffu, mx1, o));
        }
        float mn0 = fmaxf(mrow0, mx0), mn1 = fmaxf(mrow1, mx1);
        float alpha0 = exp2f(mrow0 - mn0), alpha1 = exp2f(mrow1 - mn1);
        mrow0 = mn0; mrow1 = mn1;
        float sum0 = 0.f, sum1 = 0.f;
        #pragma unroll
        for (int nt = 0; nt < 8; nt++) {
            S[nt][0] = exp2f(S[nt][0] - mn0); sum0 += S[nt][0];
            S[nt][1] = exp2f(S[nt][1] - mn0); sum0 += S[nt][1];
            S[nt][2] = exp2f(S[nt][2] - mn1); sum1 += S[nt][2];
            S[nt][3] = exp2f(S[nt][3] - mn1); sum1 += S[nt][3];
        }
        #pragma unroll
        for (int o = 1; o <= 2; o <<= 1) {
            sum0 += __shfl_xor_sync(0xffffffffu, sum0, o);
            sum1 += __shfl_xor_sync(0xffffffffu, sum1, o);
        }
        lrow0 = lrow0 * alpha0 + sum0;
        lrow1 = lrow1 * alpha1 + sum1;

        uint32_t ph[4][4], pl[4][4];
        #pragma unroll
        for (int j = 0; j < 4; j++) {
            split2(S[2*j][0],   S[2*j][1],   ph[j][0], pl[j][0]);
            split2(S[2*j][2],   S[2*j][3],   ph[j][1], pl[j][1]);
            split2(S[2*j+1][0], S[2*j+1][1], ph[j][2], pl[j][2]);
            split2(S[2*j+1][2], S[2*j+1][3], ph[j][3], pl[j][3]);
        }

        #pragma unroll
        for (int nt = 0; nt < 8; nt++) {
            Oacc[nt][0] *= alpha0; Oacc[nt][1] *= alpha0;
            Oacc[nt][2] *= alpha1; Oacc[nt][3] *= alpha1;
        }

        uint32_t vb = kb + 2 * KPLB;
        #pragma unroll
        for (int np = 0; np < 4; np++) {
            #pragma unroll
            for (int j = 0; j < 4; j++) {
                uint32_t vo = vb +
                    ((np * 16 + ((lane >> 4) << 3) + (lane & 7)) * KPAD
                     + j * 16 + (((lane >> 3) & 1) << 3)) * 2;
                uint32_t vh4[4], vl4[4];
                ldsm_x4(vh4, vo);
                ldsm_x4(vl4, vo + KPLB);
                mma_bf16(Oacc[np*2],   ph[j], vh4);
                mma_bf16(Oacc[np*2+1], ph[j], vh4 + 2);
                mma_bf16(Oacc[np*2],   ph[j], vl4);
                mma_bf16(Oacc[np*2+1], ph[j], vl4 + 2);
                mma_bf16(Oacc[np*2],   pl[j], vh4);
                mma_bf16(Oacc[np*2+1], pl[j], vh4 + 2);
            }
        }
        __syncthreads();
    }

    float inv0 = 1.f / lrow0, inv1 = 1.f / lrow1;
    int r0 = t0 + wid * 16 + (lane >> 2);
    int r1 = r0 + 8;
    #pragma unroll
    for (int nt = 0; nt < 8; nt++) {
        int col = h * CH + nt * 8 + 2 * (lane & 3);
        uint32_t hp, lp;
        split2(Oacc[nt][0] * inv0, Oacc[nt][1] * inv0, hp, lp);
        size_t o0 = ((size_t)batch * Lsp + r0) * Cch + col;
        *(uint32_t*)(ath + o0) = hp;
        *(uint32_t*)(atl + o0) = lp;
        split2(Oacc[nt][2] * inv1, Oacc[nt][3] * inv1, hp, lp);
        size_t o1 = ((size_t)batch * Lsp + r1) * Cch + col;
        *(uint32_t*)(ath + o1) = hp;
        *(uint32_t*)(atl + o1) = lp;
    }
}

// ---------------------------------------------------------------------------
// Launch
// ---------------------------------------------------------------------------
extern "C" void kernel_launch(void* const* d_in, const int* in_sizes, int n_in,
                              void* d_out, int out_size)
{
    const float* x      = (const float*)d_in[0];
    const float* norm_w = (const float*)d_in[1];
    const float* norm_b = (const float*)d_in[2];
    const float* qkv_w  = (const float*)d_in[3];
    const float* qkv_b  = (const float*)d_in[4];
    const float* proj_w = (const float*)d_in[5];
    const float* proj_b = (const float*)d_in[6];
    float* out = (float*)d_out;

    __nv_bfloat16 *xth, *xtl, *qh, *ql, *ath, *atl, *wqh, *wql, *wph, *wpl;
    cudaGetSymbolAddress((void**)&xth, g_xth);
    cudaGetSymbolAddress((void**)&xtl, g_xtl);
    cudaGetSymbolAddress((void**)&qh,  g_qh);
    cudaGetSymbolAddress((void**)&ql,  g_ql);
    cudaGetSymbolAddress((void**)&ath, g_ath);
    cudaGetSymbolAddress((void**)&atl, g_atl);
    cudaGetSymbolAddress((void**)&wqh, g_wqh);
    cudaGetSymbolAddress((void**)&wql, g_wql);
    cudaGetSymbolAddress((void**)&wph, g_wph);
    cudaGetSymbolAddress((void**)&wpl, g_wpl);

    cudaFuncSetAttribute(gemm_mma, cudaFuncAttributeMaxDynamicSharedMemorySize, GSMEM);
    cudaFuncSetAttribute(attn_mma, cudaFuncAttributeMaxDynamicSharedMemorySize, ASMEM);

    wsplit_kernel<<<(3*Cch*Cch/4 + 255)/256, 256>>>(qkv_w, wqh, wql, 3*Cch*Cch/4);
    wsplit_kernel<<<(Cch*Cch/4 + 255)/256, 256>>>(proj_w, wph, wpl, Cch*Cch/4);

    gn_kernel<<<Bsz * 32, 256>>>(x, norm_w, norm_b, xth, xtl);

    // qkv: [1536,512] @ [512,1024] per batch
    gemm_mma<<<dim3(Lsp/128, (3*Cch)/128, Bsz), 256, GSMEM>>>(
        wqh, wql, xth, xtl, qkv_b, nullptr, nullptr, qh, ql, 3*Cch);

    attn_mma<<<dim3(Lsp/128, Bsz*NH), 256, ASMEM>>>(qh, ql, ath, atl);

    // proj: [512,512] @ [512,1024] per batch + bias + residual
    gemm_mma<<<dim3(Lsp/128, Cch/128, Bsz), 256, GSMEM>>>(
        wph, wpl, ath, atl, proj_b, x, out, nullptr, nullptr, Cch);
}

// round 17
// speedup vs baseline: 3.1770x; 1.0698x over previous
#include <cuda_runtime.h>
#include <cuda_bf16.h>
#include <cstdint>

// ---------------------------------------------------------------------------
// AttentionBlock: B=16, C=512, H=W=32 (L=1024), 32 groups, 8 heads (ch=64)
// GroupNorm(->bf16 hi/lo, transposed) -> mma.sync qkv GEMM (bf16 hi/lo out,
// q pre-scaled incl. log2e) -> mma.sync flash attention (3-stage cp.async
// ring, TQ=128, exp2 softmax, 2 CTAs/SM) -> mma.sync proj GEMM + residual.
// All matmuls: split-bf16 (hi+lo), 3 MMAs ~ fp32 precision (m16n8k16).
// GEMM v3b: CTA 128x128 (2 CTAs/SM), BK=32, 3-stage cp.async ring,
// XOR-chunk swizzle, single __syncthreads per stage.
// Attn v3: same ring recipe; Q staging SMEM reused as ring buffer 0;
// ex2.approx softmax; 1-instr bf16x2 packing.
// ---------------------------------------------------------------------------

#define Bsz  16
#define Cch  512
#define Lsp  1024
#define NH   8
#define CH   64
#define EPSV 1e-4f

__device__ __nv_bfloat16 g_xth[Bsz * Lsp * Cch];   // X^T hi [b][l][c]
__device__ __nv_bfloat16 g_xtl[Bsz * Lsp * Cch];   // X^T lo
__device__ __nv_bfloat16 g_qh [Bsz * 3*Cch * Lsp]; // qkv hi [b][3C][l] (q scaled)
__device__ __nv_bfloat16 g_ql [Bsz * 3*Cch * Lsp]; // qkv lo
__device__ __nv_bfloat16 g_ath[Bsz * Lsp * Cch];   // A^T hi [b][l][c]
__device__ __nv_bfloat16 g_atl[Bsz * Lsp * Cch];   // A^T lo
__device__ __nv_bfloat16 g_wqh[3*Cch * Cch];       // qkv_w hi [M,K]
__device__ __nv_bfloat16 g_wql[3*Cch * Cch];
__device__ __nv_bfloat16 g_wph[Cch * Cch];         // proj_w hi
__device__ __nv_bfloat16 g_wpl[Cch * Cch];

// q pre-scale: ch^-0.5 (both sides folded) * log2(e) for exp2-domain softmax
#define QSCALE (0.125f * 1.44269504088896f)

// ---------------------------------------------------------------------------
// PTX helpers
// ---------------------------------------------------------------------------
__device__ __forceinline__ uint32_t smem_to_u32(const void* p) {
    uint32_t a;
    asm("{ .reg .u64 t; cvta.to.shared.u64 t, %1; cvt.u32.u64 %0, t; }"
        : "=r"(a) : "l"(p));
    return a;
}
__device__ __forceinline__ void mma_bf16(float* d, const uint32_t* a, const uint32_t* b) {
    asm volatile(
        "mma.sync.aligned.m16n8k16.row.col.f32.bf16.bf16.f32 "
        "{%0,%1,%2,%3}, {%4,%5,%6,%7}, {%8,%9}, {%0,%1,%2,%3};\n"
        : "+f"(d[0]), "+f"(d[1]), "+f"(d[2]), "+f"(d[3])
        : "r"(a[0]), "r"(a[1]), "r"(a[2]), "r"(a[3]), "r"(b[0]), "r"(b[1]));
}
__device__ __forceinline__ void ldsm_x4(uint32_t* r, uint32_t addr) {
    asm volatile("ldmatrix.sync.aligned.m8n8.x4.shared.b16 {%0,%1,%2,%3}, [%4];"
        : "=r"(r[0]), "=r"(r[1]), "=r"(r[2]), "=r"(r[3]) : "r"(addr));
}
__device__ __forceinline__ void ldsm_x4_trans(uint32_t* r, uint32_t addr) {
    asm volatile("ldmatrix.sync.aligned.m8n8.x4.trans.shared.b16 {%0,%1,%2,%3}, [%4];"
        : "=r"(r[0]), "=r"(r[1]), "=r"(r[2]), "=r"(r[3]) : "r"(addr));
}
#define CP_ASYNC16(sm, gm) \
    asm volatile("cp.async.cg.shared.global [%0], [%1], 16;" :: "r"(sm), "l"(gm))
#define CP_COMMIT() asm volatile("cp.async.commit_group;" ::: "memory")
#define CP_WAIT1()  asm volatile("cp.async.wait_group 1;" ::: "memory")
#define CP_WAIT0()  asm volatile("cp.async.wait_group 0;" ::: "memory")

// guaranteed-MUFU exp2
__device__ __forceinline__ float ex2f(float x) {
    float y;
    asm("ex2.approx.f32 %0, %1;" : "=f"(y) : "f"(x));
    return y;
}

// hi/lo bf16 split of two floats -> packed bf16x2 words (1-instr cvt path)
__device__ __forceinline__ void split2(float v0, float v1, uint32_t& hp, uint32_t& lp) {
    asm("cvt.rn.bf16x2.f32 %0, %1, %2;" : "=r"(hp) : "f"(v1), "f"(v0));
    float h0 = __uint_as_float(hp << 16);
    float h1 = __uint_as_float(hp & 0xffff0000u);
    float l0 = v0 - h0;
    float l1 = v1 - h1;
    asm("cvt.rn.bf16x2.f32 %0, %1, %2;" : "=r"(lp) : "f"(l1), "f"(l0));
}

// ---------------------------------------------------------------------------
// weight split fp32 -> bf16 hi/lo
// ---------------------------------------------------------------------------
__global__ __launch_bounds__(256) void wsplit_kernel(
    const float* __restrict__ in, __nv_bfloat16* __restrict__ hi,
    __nv_bfloat16* __restrict__ lo, int n4)
{
    int i = blockIdx.x * 256 + threadIdx.x;
    if (i >= n4) return;
    float4 v = ((const float4*)in)[i];
    uint32_t h0, l0, h1, l1;
    split2(v.x, v.y, h0, l0);
    split2(v.z, v.w, h1, l1);
    ((uint2*)hi)[i] = make_uint2(h0, h1);
    ((uint2*)lo)[i] = make_uint2(l0, l1);
}

// ---------------------------------------------------------------------------
// GroupNorm -> transposed bf16 hi/lo Xt[b][l][c]
// ---------------------------------------------------------------------------
#define SM8S 1028
__global__ __launch_bounds__(256) void gn_kernel(
    const float* __restrict__ x, const float* __restrict__ w,
    const float* __restrict__ bb,
    __nv_bfloat16* __restrict__ xth, __nv_bfloat16* __restrict__ xtl)
{
    int batch = blockIdx.x >> 5;
    int g     = blockIdx.x & 31;
    const size_t base = ((size_t)batch * Cch + (size_t)g * 16) * Lsp;
    const float* xp = x + base;

    float s = 0.f, s2 = 0.f;
    for (int i = threadIdx.x * 4; i < 16 * Lsp; i += 256 * 4) {
        float4 v = *(const float4*)(xp + i);
        s  += v.x + v.y + v.z + v.w;
        s2 += v.x*v.x + v.y*v.y + v.z*v.z + v.w*v.w;
    }
    #pragma unroll
    for (int o = 16; o; o >>= 1) {
        s  += __shfl_xor_sync(0xffffffffu, s,  o);
        s2 += __shfl_xor_sync(0xffffffffu, s2, o);
    }
    __shared__ float sA[8], sB[8];
    __shared__ float sm8[8 * SM8S];
    int warp = threadIdx.x >> 5, lane = threadIdx.x & 31;
    if (lane == 0) { sA[warp] = s; sB[warp] = s2; }
    __syncthreads();
    if (threadIdx.x == 0) {
        float S = 0.f, S2 = 0.f;
        #pragma unroll
        for (int i = 0; i < 8; i++) { S += sA[i]; S2 += sB[i]; }
        float mu  = S  * (1.f / (16.f * Lsp));
        float var = S2 * (1.f / (16.f * Lsp)) - mu * mu;
        sA[0] = mu;
        sB[0] = rsqrtf(var + EPSV);
    }
    __syncthreads();
    float mu = sA[0], rstd = sB[0];
    int tid = threadIdx.x;

    #pragma unroll
    for (int half = 0; half < 2; half++) {
        if (half) __syncthreads();
        for (int i = tid * 4; i < 8 * Lsp; i += 256 * 4) {
            int r = i >> 10, col = i & 1023;
            int c = g * 16 + half * 8 + r;
            float sw = w[c] * rstd;
            float sb = bb[c] - mu * sw;
            float4 v = *(const float4*)(xp + (size_t)(half * 8 + r) * Lsp + col);
            v.x = v.x * sw + sb; v.y = v.y * sw + sb;
            v.z = v.z * sw + sb; v.w = v.w * sw + sb;
            *(float4*)(&sm8[r * SM8S + col]) = v;
        }
        __syncthreads();
        for (int n = tid; n < Lsp; n += 256) {
            uint32_t hp[4], lp[4];
            #pragma unroll
            for (int c2 = 0; c2 < 4; c2++)
                split2(sm8[(2*c2) * SM8S + n], sm8[(2*c2+1) * SM8S + n], hp[c2], lp[c2]);
            size_t o = ((size_t)batch * Lsp + n) * Cch + g * 16 + half * 8;
            *(uint4*)(xth + o) = make_uint4(hp[0], hp[1], hp[2], hp[3]);
            *(uint4*)(xtl + o) = make_uint4(lp[0], lp[1], lp[2], lp[3]);
        }
    }
}

// ---------------------------------------------------------------------------
// split-bf16 GEMM v3b (unchanged from R13): CTA 128x128, BK=32, 3-stage ring,
// XOR chunk swizzle, one barrier/stage, 2 CTAs/SM.
// ---------------------------------------------------------------------------
#define GROWB  64
#define GPLB   (128 * GROWB)             // 8192
#define GSTGB  (4 * GPLB)                // 32768
#define GSMEM  (3 * GSTGB)               // 98304

__global__ __launch_bounds__(256, 2) void gemm_mma(
    const __nv_bfloat16* __restrict__ Wh, const __nv_bfloat16* __restrict__ Wl,
    const __nv_bfloat16* __restrict__ Xh, const __nv_bfloat16* __restrict__ Xl,
    const float* __restrict__ bias, const float* __restrict__ resid,
    float* __restrict__ C,
    __nv_bfloat16* __restrict__ Oh, __nv_bfloat16* __restrict__ Ol, int M)
{
    extern __shared__ char smem[];
    uint32_t sb = smem_to_u32(smem);
    int tid = threadIdx.x;
    int wid = tid >> 5, lane = tid & 31;
    int m0 = blockIdx.y << 7, n0 = blockIdx.x << 7, b = blockIdx.z;

    const __nv_bfloat16* gsrc[8];
    uint32_t soff[8];
    #pragma unroll
    for (int i = 0; i < 8; i++) {
        int c = i * 256 + tid;
        int plane = c >> 9, row = (c >> 2) & 127, kc = c & 3;
        const __nv_bfloat16* gp;
        if      (plane == 0) gp = Wh + (size_t)(m0 + row) * Cch;
        else if (plane == 1) gp = Wl + (size_t)(m0 + row) * Cch;
        else if (plane == 2) gp = Xh + ((size_t)b * Lsp + n0 + row) * Cch;
        else                 gp = Xl + ((size_t)b * Lsp + n0 + row) * Cch;
        gsrc[i] = gp + kc * 8;
        soff[i] = plane * GPLB + row * GROWB + ((kc ^ ((row >> 1) & 3)) << 4);
    }

    #pragma unroll
    for (int i = 0; i < 8; i++) CP_ASYNC16(sb + soff[i], gsrc[i]);
    CP_COMMIT();
    #pragma unroll
    for (int i = 0; i < 8; i++) CP_ASYNC16(sb + GSTGB + soff[i], gsrc[i] + 32);
    CP_COMMIT();

    int wm = wid >> 1, wn = wid & 1;
    float acc[2][8][4];
    #pragma unroll
    for (int mt = 0; mt < 2; mt++)
        #pragma unroll
        for (int nt = 0; nt < 8; nt++)
            #pragma unroll
            for (int q = 0; q < 4; q++) acc[mt][nt][q] = 0.f;

    uint32_t aoff[2][2], boff[2][4];
    #pragma unroll
    for (int ks = 0; ks < 2; ks++) {
        #pragma unroll
        for (int mt = 0; mt < 2; mt++) {
            int r = wm * 32 + mt * 16 + (lane & 15);
            int ck = ks * 2 + (lane >> 4);
            aoff[ks][mt] = r * GROWB + ((ck ^ ((r >> 1) & 3)) << 4);
        }
        #pragma unroll
        for (int ntp = 0; ntp < 4; ntp++) {
            int r = wn * 64 + ntp * 16 + (lane & 7) + ((lane >> 4) << 3);
            int ck = ks * 2 + ((lane >> 3) & 1);
            boff[ks][ntp] = 2 * GPLB + r * GROWB + ((ck ^ ((r >> 1) & 3)) << 4);
        }
    }

    int buf = 0, pbuf = 2;
    #pragma unroll 1
    for (int s = 0; s < 16; s++) {
        CP_WAIT1();
        __syncthreads();
        if (s + 2 < 16) {
            int k0 = (s + 2) * 32;
            uint32_t nb = (uint32_t)pbuf * GSTGB;
            #pragma unroll
            for (int i = 0; i < 8; i++) CP_ASYNC16(sb + nb + soff[i], gsrc[i] + k0);
        }
        CP_COMMIT();

        uint32_t sbase = sb + (uint32_t)buf * GSTGB;
        #pragma unroll
        for (int ks = 0; ks < 2; ks++) {
            uint32_t ah[2][4], al[2][4];
            #pragma unroll
            for (int mt = 0; mt < 2; mt++) {
                uint32_t ao = sbase + aoff[ks][mt];
                ldsm_x4(ah[mt], ao);
                ldsm_x4(al[mt], ao + GPLB);
            }
            #pragma unroll
            for (int ntp = 0; ntp < 4; ntp++) {
                uint32_t bo = sbase + boff[ks][ntp];
                uint32_t bh4[4], bl4[4];
                ldsm_x4(bh4, bo);
                ldsm_x4(bl4, bo + GPLB);
                #pragma unroll
                for (int mt = 0; mt < 2; mt++)
                    #pragma unroll
                    for (int sub = 0; sub < 2; sub++)
                        mma_bf16(acc[mt][ntp*2+sub], ah[mt], bh4 + sub * 2);
                #pragma unroll
                for (int mt = 0; mt < 2; mt++)
                    #pragma unroll
                    for (int sub = 0; sub < 2; sub++)
                        mma_bf16(acc[mt][ntp*2+sub], ah[mt], bl4 + sub * 2);
                #pragma unroll
                for (int mt = 0; mt < 2; mt++)
                    #pragma unroll
                    for (int sub = 0; sub < 2; sub++)
                        mma_bf16(acc[mt][ntp*2+sub], al[mt], bh4 + sub * 2);
            }
        }
        buf  = (buf  == 2) ? 0 : buf  + 1;
        pbuf = (pbuf == 2) ? 0 : pbuf + 1;
    }

    #pragma unroll
    for (int mt = 0; mt < 2; mt++) {
        int r0 = m0 + wm * 32 + mt * 16 + (lane >> 2);
        #pragma unroll
        for (int half = 0; half < 2; half++) {
            int r = r0 + half * 8;
            float bz = bias[r];
            #pragma unroll
            for (int nt = 0; nt < 8; nt++) {
                int col = n0 + wn * 64 + nt * 8 + 2 * (lane & 3);
                float v0 = acc[mt][nt][half * 2 + 0] + bz;
                float v1 = acc[mt][nt][half * 2 + 1] + bz;
                if (C) {
                    size_t o = ((size_t)b * M + r) * Lsp + col;
                    float2 rv = *(const float2*)(resid + o);
                    *(float2*)(C + o) = make_float2(v0 + rv.x, v1 + rv.y);
                } else {
                    if (r < Cch) { v0 *= QSCALE; v1 *= QSCALE; }
                    uint32_t hp, lp;
                    split2(v0, v1, hp, lp);
                    size_t o = ((size_t)b * M + r) * Lsp + col;
                    *(uint32_t*)(Oh + o) = hp;
                    *(uint32_t*)(Ol + o) = lp;
                }
            }
        }
    }
}

// ---------------------------------------------------------------------------
// flash attention v3: TQ=128, 256 threads (8 warps x m16).
// 3-stage cp.async KV ring (buffer 0 = reused Q staging region), XOR chunk
// swizzle, single __syncthreads per tile, exp2 softmax, 2 CTAs/SM.
// SMEM: [0,32K) ring buf0 (Q planes during prologue), [32K,64K) buf1,
//       [64K,96K) buf2. Q plane = 64 rows x 256B; KV stage = 4 planes
//       (Kh Kl Vh Vl) of 64 rows x 128B.
// ---------------------------------------------------------------------------
#define QROWB  256
#define QPLB2  (64 * QROWB)          // 16384
#define KROWB  128
#define KPLB2  (64 * KROWB)          // 8192
#define KVSTG2 (4 * KPLB2)           // 32768
#define ASMEM  (3 * KVSTG2)          // 98304

__device__ __forceinline__ void kv_stage(
    uint32_t dst, const __nv_bfloat16* qh, const __nv_bfloat16* ql,
    size_t krow, size_t vrow, int s0, int tid)
{
    #pragma unroll
    for (int i = 0; i < 8; i++) {
        int c = i * 256 + tid;
        int plane = c >> 9, row = (c >> 3) & 63, cc = c & 7;
        size_t grow = (plane < 2 ? krow : vrow) + row;
        const __nv_bfloat16* src = ((plane & 1) ? ql : qh) + grow * Lsp + s0 + cc * 8;
        CP_ASYNC16(dst + plane * KPLB2 + row * KROWB + ((cc ^ (row & 7)) << 4), src);
    }
}

__global__ __launch_bounds__(256, 2) void attn_mma(
    const __nv_bfloat16* __restrict__ qh, const __nv_bfloat16* __restrict__ ql,
    __nv_bfloat16* __restrict__ ath, __nv_bfloat16* __restrict__ atl)
{
    extern __shared__ char smem[];
    uint32_t sb = smem_to_u32(smem);
    int tid = threadIdx.x;
    int wid = tid >> 5, lane = tid & 31;
    int bh = blockIdx.y;
    int batch = bh >> 3, h = bh & 7;
    int t0 = blockIdx.x << 7;

    size_t qrow = (size_t)batch * (3 * Cch) + h * CH;
    size_t krow = qrow + Cch;
    size_t vrow = qrow + 2 * Cch;

    // prologue: Q -> buf0 region (group 0, shared with KV stage 0)
    #pragma unroll
    for (int i = 0; i < 8; i++) {
        int c = i * 256 + tid;
        int plane = c >> 10, row = (c >> 4) & 63, cc = c & 15;
        const __nv_bfloat16* src = (plane ? ql : qh) + (qrow + row) * Lsp + t0 + cc * 8;
        CP_ASYNC16(sb + plane * QPLB2 + row * QROWB + ((cc ^ (row & 7)) << 4), src);
    }
    kv_stage(sb + KVSTG2, qh, ql, krow, vrow, 0, tid);
    CP_COMMIT();                                   // group0: Q + stage0
    kv_stage(sb + 2 * KVSTG2, qh, ql, krow, vrow, 64, tid);
    CP_COMMIT();                                   // group1: stage1
    CP_WAIT1();                                    // group0 complete
    __syncthreads();

    // Q fragments (A: m=t, k=ch), register-resident; swizzled trans loads
    uint32_t aqh[4][4], aql[4][4];
    #pragma unroll
    for (int k = 0; k < 4; k++) {
        int r  = k * 16 + ((lane >> 4) << 3) + (lane & 7);
        int cc = wid * 2 + ((lane >> 3) & 1);
        uint32_t ao = sb + r * QROWB + ((cc ^ (r & 7)) << 4);
        ldsm_x4_trans(aqh[k], ao);
        ldsm_x4_trans(aql[k], ao + QPLB2);
    }
    __syncthreads();                               // buf0 free for ring reuse

    float Oacc[8][4];
    #pragma unroll
    for (int nt = 0; nt < 8; nt++)
        #pragma unroll
        for (int q = 0; q < 4; q++) Oacc[nt][q] = 0.f;
    float mrow0 = -INFINITY, mrow1 = -INFINITY, lrow0 = 0.f, lrow1 = 0.f;

    #pragma unroll 1
    for (int s = 0; s < 16; s++) {
        CP_WAIT1();              // stage s complete (newest, s+1, may pend)
        __syncthreads();         // stage s visible; stage s-1 readers done
        if (s + 2 < 16) {
            // buffer(s+2) = (s+3)%3 == s%3 : the buffer stage s-1 vacated
            kv_stage(sb + (uint32_t)(s % 3) * KVSTG2, qh, ql, krow, vrow,
                     (s + 2) * 64, tid);
        }
        CP_COMMIT();

        uint32_t kb = sb + (uint32_t)((s + 1) % 3) * KVSTG2;

        // S = Q K^T (hh + hl + lh); logits in log2 domain
        float S[8][4];
        #pragma unroll
        for (int nt = 0; nt < 8; nt++) { S[nt][0]=S[nt][1]=S[nt][2]=S[nt][3]=0.f; }
        #pragma unroll
        for (int k = 0; k < 4; k++) {
            int r = k * 16 + (((lane >> 3) & 1) << 3) + (lane & 7);
            #pragma unroll
            for (int np = 0; np < 4; np++) {
                int cc = np * 2 + (lane >> 4);
                uint32_t ko = kb + r * KROWB + ((cc ^ (r & 7)) << 4);
                uint32_t bh4[4], bl4[4];
                ldsm_x4_trans(bh4, ko);
                ldsm_x4_trans(bl4, ko + KPLB2);
                mma_bf16(S[np*2],   aqh[k], bh4);
                mma_bf16(S[np*2+1], aqh[k], bh4 + 2);
                mma_bf16(S[np*2],   aqh[k], bl4);
                mma_bf16(S[np*2+1], aqh[k], bl4 + 2);
                mma_bf16(S[np*2],   aql[k], bh4);
                mma_bf16(S[np*2+1], aql[k], bh4 + 2);
            }
        }

        // online softmax (rows r=lane/4 -> c0,c1 ; r+8 -> c2,c3)
        float mx0 = -INFINITY, mx1 = -INFINITY;
        #pragma unroll
        for (int nt = 0; nt < 8; nt++) {
            mx0 = fmaxf(mx0, fmaxf(S[nt][0], S[nt][1]));
            mx1 = fmaxf(mx1, fmaxf(S[nt][2], S[nt][3]));
        }
        #pragma unroll
        for (int o = 1; o <= 2; o <<= 1) {
            mx0 = fmaxf(mx0, __shfl_xor_sync(0xffffffffu, mx0, o));
            mx1 = fmaxf(mx1, __shfl_xor_sync(0xffffffffu, mx1, o));
        }
        float mn0 = fmaxf(mrow0, mx0), mn1 = fmaxf(mrow1, mx1);
        float alpha0 = ex2f(mrow0 - mn0), alpha1 = ex2f(mrow1 - mn1);
        mrow0 = mn0; mrow1 = mn1;
        float sum0 = 0.f, sum1 = 0.f;
        #pragma unroll
        for (int nt = 0; nt < 8; nt++) {
            S[nt][0] = ex2f(S[nt][0] - mn0); sum0 += S[nt][0];
            S[nt][1] = ex2f(S[nt][1] - mn0); sum0 += S[nt][1];
            S[nt][2] = ex2f(S[nt][2] - mn1); sum1 += S[nt][2];
            S[nt][3] = ex2f(S[nt][3] - mn1); sum1 += S[nt][3];
        }
        #pragma unroll
        for (int o = 1; o <= 2; o <<= 1) {
            sum0 += __shfl_xor_sync(0xffffffffu, sum0, o);
            sum1 += __shfl_xor_sync(0xffffffffu, sum1, o);
        }
        lrow0 = lrow0 * alpha0 + sum0;
        lrow1 = lrow1 * alpha1 + sum1;

        // pack P -> A frags (hi/lo): step j covers s-dim k16 = S tiles 2j,2j+1
        uint32_t ph[4][4], pl[4][4];
        #pragma unroll
        for (int j = 0; j < 4; j++) {
            split2(S[2*j][0],   S[2*j][1],   ph[j][0], pl[j][0]);
            split2(S[2*j][2],   S[2*j][3],   ph[j][1], pl[j][1]);
            split2(S[2*j+1][0], S[2*j+1][1], ph[j][2], pl[j][2]);
            split2(S[2*j+1][2], S[2*j+1][3], ph[j][3], pl[j][3]);
        }

        #pragma unroll
        for (int nt = 0; nt < 8; nt++) {
            Oacc[nt][0] *= alpha0; Oacc[nt][1] *= alpha0;
            Oacc[nt][2] *= alpha1; Oacc[nt][3] *= alpha1;
        }

        // O += P V (hh + hl + lh); V plane non-trans x4 loads
        uint32_t vb = kb + 2 * KPLB2;
        #pragma unroll
        for (int np = 0; np < 4; np++) {
            int r = np * 16 + ((lane >> 4) << 3) + (lane & 7);
            #pragma unroll
            for (int j = 0; j < 4; j++) {
                int cc = j * 2 + ((lane >> 3) & 1);
                uint32_t vo = vb + r * KROWB + ((cc ^ (r & 7)) << 4);
                uint32_t vh4[4], vl4[4];
                ldsm_x4(vh4, vo);
                ldsm_x4(vl4, vo + KPLB2);
                mma_bf16(Oacc[np*2],   ph[j], vh4);
                mma_bf16(Oacc[np*2+1], ph[j], vh4 + 2);
                mma_bf16(Oacc[np*2],   ph[j], vl4);
                mma_bf16(Oacc[np*2+1], ph[j], vl4 + 2);
                mma_bf16(Oacc[np*2],   pl[j], vh4);
                mma_bf16(Oacc[np*2+1], pl[j], vh4 + 2);
            }
        }
    }

    // epilogue: O /= l, split hi/lo, write transposed At[b][l][c]
    float inv0 = 1.f / lrow0, inv1 = 1.f / lrow1;
    int r0 = t0 + wid * 16 + (lane >> 2);
    int r1 = r0 + 8;
    #pragma unroll
    for (int nt = 0; nt < 8; nt++) {
        int col = h * CH + nt * 8 + 2 * (lane & 3);
        uint32_t hp, lp;
        split2(Oacc[nt][0] * inv0, Oacc[nt][1] * inv0, hp, lp);
        size_t o0 = ((size_t)batch * Lsp + r0) * Cch + col;
        *(uint32_t*)(ath + o0) = hp;
        *(uint32_t*)(atl + o0) = lp;
        split2(Oacc[nt][2] * inv1, Oacc[nt][3] * inv1, hp, lp);
        size_t o1 = ((size_t)batch * Lsp + r1) * Cch + col;
        *(uint32_t*)(ath + o1) = hp;
        *(uint32_t*)(atl + o1) = lp;
    }
}

// ---------------------------------------------------------------------------
// Launch
// ---------------------------------------------------------------------------
extern "C" void kernel_launch(void* const* d_in, const int* in_sizes, int n_in,
                              void* d_out, int out_size)
{
    const float* x      = (const float*)d_in[0];
    const float* norm_w = (const float*)d_in[1];
    const float* norm_b = (const float*)d_in[2];
    const float* qkv_w  = (const float*)d_in[3];
    const float* qkv_b  = (const float*)d_in[4];
    const float* proj_w = (const float*)d_in[5];
    const float* proj_b = (const float*)d_in[6];
    float* out = (float*)d_out;

    __nv_bfloat16 *xth, *xtl, *qh, *ql, *ath, *atl, *wqh, *wql, *wph, *wpl;
    cudaGetSymbolAddress((void**)&xth, g_xth);
    cudaGetSymbolAddress((void**)&xtl, g_xtl);
    cudaGetSymbolAddress((void**)&qh,  g_qh);
    cudaGetSymbolAddress((void**)&ql,  g_ql);
    cudaGetSymbolAddress((void**)&ath, g_ath);
    cudaGetSymbolAddress((void**)&atl, g_atl);
    cudaGetSymbolAddress((void**)&wqh, g_wqh);
    cudaGetSymbolAddress((void**)&wql, g_wql);
    cudaGetSymbolAddress((void**)&wph, g_wph);
    cudaGetSymbolAddress((void**)&wpl, g_wpl);

    cudaFuncSetAttribute(gemm_mma, cudaFuncAttributeMaxDynamicSharedMemorySize, GSMEM);
    cudaFuncSetAttribute(attn_mma, cudaFuncAttributeMaxDynamicSharedMemorySize, ASMEM);

    wsplit_kernel<<<(3*Cch*Cch/4 + 255)/256, 256>>>(qkv_w, wqh, wql, 3*Cch*Cch/4);
    wsplit_kernel<<<(Cch*Cch/4 + 255)/256, 256>>>(proj_w, wph, wpl, Cch*Cch/4);

    gn_kernel<<<Bsz * 32, 256>>>(x, norm_w, norm_b, xth, xtl);

    // qkv: [1536,512] @ [512,1024] per batch
    gemm_mma<<<dim3(Lsp/128, (3*Cch)/128, Bsz), 256, GSMEM>>>(
        wqh, wql, xth, xtl, qkv_b, nullptr, nullptr, qh, ql, 3*Cch);

    attn_mma<<<dim3(Lsp/128, Bsz*NH), 256, ASMEM>>>(qh, ql, ath, atl);

    // proj: [512,512] @ [512,1024] per batch + bias + residual
    gemm_mma<<<dim3(Lsp/128, Cch/128, Bsz), 256, GSMEM>>>(
        wph, wpl, ath, atl, proj_b, x, out, nullptr, nullptr, Cch);
}